// round 11
// baseline (speedup 1.0000x reference)
#include <cuda_runtime.h>
#include <cuda_bf16.h>
#include <cstdint>
#include <cstddef>

// Problem constants
#define N_SRC0   286000
#define N_DST0   11000
#define N_E0     275000
#define N_DST1   1000
#define N_E1     10000
#define F_IN     602
#define HID      256
#define NCLS     41
#define KPAD     608          // 19 chunks of 32
#define F2       (F_IN / 2)   // 301
#define P2       (KPAD / 2)   // 304
#define KCH      19           // K-chunks per phase

// ---------------- scratch (device globals; no runtime allocation) ----------
__device__ int g_cnt0[N_DST0];
__device__ int g_cur0[N_DST0];
__device__ int g_off0[N_DST0 + 1];
__device__ int g_src0[N_E0];
__device__ int g_cnt1[N_DST1];
__device__ int g_cur1[N_DST1];
__device__ int g_off1[N_DST1 + 1];
__device__ int g_src1[N_E1];

// tf32-rounded fp32 operand buffers (padded to KPAD)
__device__ __align__(16) float g_xt  [(size_t)N_DST0 * KPAD];   // x[:11000] rna-rounded
__device__ __align__(16) float g_hagg[(size_t)N_DST0 * KPAD];   // layer-0 mean agg, rna-rounded
__device__ __align__(16) float g_wts [256 * KPAD];              // Wself0^T  [n][k]
__device__ __align__(16) float g_wtn [256 * KPAD];              // Wneigh0^T [n][k]

__device__ float g_h[(size_t)N_DST0 * HID];

// round-to-nearest tf32 (unbiased)
__device__ __forceinline__ float tf32r(float v) {
    uint32_t o;
    asm("cvt.rna.tf32.f32 %0, %1;" : "=r"(o) : "f"(v));
    return __uint_as_float(o);
}

// ---------------- CSR build --------------------------------------------------
__global__ void k_zero() {
    int i = blockIdx.x * blockDim.x + threadIdx.x;
    if (i < N_DST0) g_cnt0[i] = 0;
    if (i < N_DST1) g_cnt1[i] = 0;
}

// fused: edge counting + weight transpose/round prep
#define CNT_BLKS  ((N_E0 + 255) / 256)           // 1075
#define PW_BLKS   ((2 * 256 * KPAD + 255) / 256) // 1216
__global__ void k_count_prepw(const int* __restrict__ e0_dst, const int* __restrict__ e1_dst,
                              const float* __restrict__ Ws, const float* __restrict__ Wn) {
    int bx = blockIdx.x;
    if (bx < CNT_BLKS) {
        int i = bx * 256 + threadIdx.x;
        if (i < N_E0) atomicAdd(&g_cnt0[e0_dst[i]], 1);
        if (i < N_E1) atomicAdd(&g_cnt1[e1_dst[i]], 1);
    } else {
        int idx = (bx - CNT_BLKS) * 256 + threadIdx.x;
        if (idx >= 2 * 256 * KPAD) return;
        int m = idx / (256 * KPAD);
        int r = idx % (256 * KPAD);
        int n = r / KPAD;
        int k = r % KPAD;
        const float* W = m ? Wn : Ws;
        float v = (k < F_IN) ? tf32r(W[(size_t)k * HID + n]) : 0.0f;
        if (m) g_wtn[n * KPAD + k] = v;
        else   g_wts[n * KPAD + k] = v;
    }
}

// scan also zeroes g_cur (it already touches every dst index)
__device__ void scan_excl(const int* cnt, int* off, int* cur, int n) {
    __shared__ int wsum[32];
    __shared__ int carry;
    const int t = threadIdx.x, lane = t & 31, w = t >> 5;
    if (t == 0) carry = 0;
    __syncthreads();
    for (int base = 0; base < n; base += 1024) {
        int i = base + t;
        int v = (i < n) ? cnt[i] : 0;
        int s = v;
        #pragma unroll
        for (int d = 1; d < 32; d <<= 1) { int u = __shfl_up_sync(~0u, s, d); if (lane >= d) s += u; }
        if (lane == 31) wsum[w] = s;
        __syncthreads();
        if (w == 0) {
            int ws = wsum[lane];
            #pragma unroll
            for (int d = 1; d < 32; d <<= 1) { int u = __shfl_up_sync(~0u, ws, d); if (lane >= d) ws += u; }
            wsum[lane] = ws;
        }
        __syncthreads();
        int woff = (w > 0) ? wsum[w - 1] : 0;
        if (i < n) { off[i] = carry + woff + s - v; cur[i] = 0; }
        __syncthreads();
        if (t == 0) carry += wsum[31];
        __syncthreads();
    }
    if (threadIdx.x == 0) off[n] = carry;
}

__global__ void k_scan() {
    if (blockIdx.x == 0) scan_excl(g_cnt0, g_off0, g_cur0, N_DST0);
    else                 scan_excl(g_cnt1, g_off1, g_cur1, N_DST1);
}

// fused: edge scatter + x round/pad prep
#define PX_BLKS ((N_DST0 * P2 + 255) / 256)   // 13063
__global__ void k_scatter_prepx(const int* __restrict__ e0_src, const int* __restrict__ e0_dst,
                                const int* __restrict__ e1_src, const int* __restrict__ e1_dst,
                                const float* __restrict__ x) {
    int bx = blockIdx.x;
    if (bx < CNT_BLKS) {
        int i = bx * 256 + threadIdx.x;
        if (i < N_E0) {
            int d = e0_dst[i];
            int p = atomicAdd(&g_cur0[d], 1);
            g_src0[g_off0[d] + p] = e0_src[i];
        }
        if (i < N_E1) {
            int d = e1_dst[i];
            int p = atomicAdd(&g_cur1[d], 1);
            g_src1[g_off1[d] + p] = e1_src[i];
        }
    } else {
        int idx = (bx - CNT_BLKS) * 256 + threadIdx.x;
        if (idx >= N_DST0 * P2) return;
        int row = idx / P2;
        int p   = idx % P2;
        float2 v = make_float2(0.f, 0.f);
        if (p < F2) v = reinterpret_cast<const float2*>(x)[(size_t)row * F2 + p];
        float2 o; o.x = tf32r(v.x); o.y = tf32r(v.y);
        reinterpret_cast<float2*>(g_xt)[(size_t)row * P2 + p] = o;
    }
}

// ---------------- layer-0 mean aggregation (big gather) ----------------------
__global__ void k_agg0(const float* __restrict__ x) {
    const int dst = blockIdx.x;
    const int beg = g_off0[dst];
    const int end = g_off0[dst + 1];
    const int t   = threadIdx.x;

    float2 acc0 = make_float2(0.f, 0.f);
    float2 acc1 = make_float2(0.f, 0.f);
    float2 acc2 = make_float2(0.f, 0.f);
    const bool has3 = (t + 256) < F2;

    int e = beg;
    for (; e + 4 <= end; e += 4) {
        const float2* r0 = reinterpret_cast<const float2*>(x + (size_t)g_src0[e + 0] * F_IN);
        const float2* r1 = reinterpret_cast<const float2*>(x + (size_t)g_src0[e + 1] * F_IN);
        const float2* r2 = reinterpret_cast<const float2*>(x + (size_t)g_src0[e + 2] * F_IN);
        const float2* r3 = reinterpret_cast<const float2*>(x + (size_t)g_src0[e + 3] * F_IN);
        float2 a0 = __ldg(r0 + t),       b0 = __ldg(r1 + t),       c0 = __ldg(r2 + t),       d0 = __ldg(r3 + t);
        float2 a1 = __ldg(r0 + t + 128), b1 = __ldg(r1 + t + 128), c1 = __ldg(r2 + t + 128), d1 = __ldg(r3 + t + 128);
        acc0.x += a0.x + b0.x + c0.x + d0.x;
        acc0.y += a0.y + b0.y + c0.y + d0.y;
        acc1.x += a1.x + b1.x + c1.x + d1.x;
        acc1.y += a1.y + b1.y + c1.y + d1.y;
        if (has3) {
            float2 a2 = __ldg(r0 + t + 256), b2 = __ldg(r1 + t + 256);
            float2 c2 = __ldg(r2 + t + 256), d2 = __ldg(r3 + t + 256);
            acc2.x += a2.x + b2.x + c2.x + d2.x;
            acc2.y += a2.y + b2.y + c2.y + d2.y;
        }
    }
    for (; e < end; ++e) {
        const float2* row = reinterpret_cast<const float2*>(x + (size_t)g_src0[e] * F_IN);
        float2 v0 = __ldg(row + t);
        float2 v1 = __ldg(row + t + 128);
        acc0.x += v0.x; acc0.y += v0.y;
        acc1.x += v1.x; acc1.y += v1.y;
        if (has3) {
            float2 v2 = __ldg(row + t + 256);
            acc2.x += v2.x; acc2.y += v2.y;
        }
    }

    const float inv = (end > beg) ? 1.0f / (float)(end - beg) : 0.0f;
    float2* o = reinterpret_cast<float2*>(g_hagg) + (size_t)dst * P2;
    float2 accs[3] = {acc0, acc1, acc2};
    #pragma unroll
    for (int j = 0; j < 3; ++j) {
        int p = t + j * 128;
        if (p >= P2) break;
        float2 ov;
        ov.x = (p < F2) ? tf32r(accs[j].x * inv) : 0.f;
        ov.y = (p < F2) ? tf32r(accs[j].y * inv) : 0.f;
        o[p] = ov;
    }
}

// ---------------- tensor-core GEMM via mma.sync (TF32, sm_80+ PTX) ----------
// h = relu([Xd | Hagg] @ [Ws; Wn] + b0).
// CTA tile 128x128; grid (86, 2); 8 warps = 4(M) x 2(N); warp tile 32x64.
// 3-stage cp.async pipeline, 38 flattened chunks spanning both phases.
#define BK        32
#define ROWPF     36                       // padded row length (floats); 36%32=4 -> frag banks 4g+tg, conflict-free
#define A_T       (128 * ROWPF * 4)        // 18432 B
#define B_T       (128 * ROWPF * 4)        // 18432 B
#define BUF_SZ    (A_T + B_T)              // 36864 B
#define NSTAGE    3
#define GEMM_SMEM (NSTAGE * BUF_SZ)        // 110592 B
#define NCH       (2 * KCH)                // 38

#define CP16(dst, src, pred) \
    asm volatile("cp.async.cg.shared.global [%0], [%1], 16, %2;" \
                 :: "r"(dst), "l"(src), "r"(pred))
#define CP_COMMIT() asm volatile("cp.async.commit_group;" ::: "memory")
#define CP_WAIT(n)  asm volatile("cp.async.wait_group %0;" :: "n"(n) : "memory")

__device__ __forceinline__ uint32_t smem_u32(const void* p) {
    uint32_t a;
    asm("{ .reg .u64 t; cvta.to.shared.u64 t, %1; cvt.u32.u64 %0, t; }" : "=r"(a) : "l"(p));
    return a;
}

__device__ __forceinline__ void mma_tf32(float* d,
                                         const uint32_t* a, const uint32_t* b) {
    asm volatile(
        "mma.sync.aligned.m16n8k8.row.col.f32.tf32.tf32.f32 "
        "{%0,%1,%2,%3}, {%4,%5,%6,%7}, {%8,%9}, {%0,%1,%2,%3};"
        : "+f"(d[0]), "+f"(d[1]), "+f"(d[2]), "+f"(d[3])
        : "r"(a[0]), "r"(a[1]), "r"(a[2]), "r"(a[3]), "r"(b[0]), "r"(b[1]));
}

__global__ __launch_bounds__(256, 2)
void k_gemm_mma(const float* __restrict__ bias) {
    extern __shared__ char smem[];
    const uint32_t sb = smem_u32(smem);
    const int tid  = threadIdx.x;
    const int lane = tid & 31;
    const int wid  = tid >> 5;
    const int warpM = wid & 3;            // 0..3 -> rows warpM*32
    const int warpN = wid >> 2;           // 0..1 -> cols warpN*64
    const int g  = lane >> 2;             // 0..7
    const int tg = lane & 3;              // 0..3
    const int rowBase = blockIdx.x * 128;
    const int colBase = blockIdx.y * 128;

    auto issue = [&](int c) {
        const int ph = (c >= KCH);
        const int kb = (c - ph * KCH) * BK;
        const float* A = ph ? g_hagg : g_xt;
        const float* B = ph ? g_wtn : g_wts;
        const uint32_t bufb = sb + (uint32_t)(c % NSTAGE) * BUF_SZ;

        // A: 128 rows x 32 floats = 1024 vec16 -> 4 per thread
        #pragma unroll
        for (int u = 0; u < 4; ++u) {
            int idx = tid + u * 256;          // 0..1023
            int row = idx >> 3, v = idx & 7;
            int grow = rowBase + row;
            int pr = (grow < N_DST0) ? 16 : 0;
            size_t gb = ((size_t)grow * KPAD + kb + v * 4) * 4;
            if (grow >= N_DST0) gb = 0;
            uint32_t so = bufb + (uint32_t)(row * (ROWPF * 4) + v * 16);
            CP16(so, (const char*)A + gb, pr);
        }
        // B: 128 rows x 32 floats = 1024 vec16 -> 4 per thread
        #pragma unroll
        for (int u = 0; u < 4; ++u) {
            int idx = tid + u * 256;          // 0..1023
            int row = idx >> 3, v = idx & 7;
            size_t gb = ((size_t)(colBase + row) * KPAD + kb + v * 4) * 4;
            uint32_t so = bufb + (uint32_t)(A_T + row * (ROWPF * 4) + v * 16);
            CP16(so, (const char*)B + gb, 16);
        }
    };

    float acc[2][8][4] = {};   // [mtile][ntile][reg]

    issue(0); CP_COMMIT();
    issue(1); CP_COMMIT();

    for (int c = 0; c < NCH; ++c) {
        if (c + 2 < NCH)      { issue(c + 2); CP_COMMIT(); CP_WAIT(2); }
        else if (c + 1 < NCH) { CP_WAIT(1); }
        else                  { CP_WAIT(0); }
        __syncthreads();

        const char* buf = smem + (c % NSTAGE) * BUF_SZ;
        const char* As = buf;
        const char* Bs = buf + A_T;

        #pragma unroll
        for (int ks = 0; ks < 4; ++ks) {
            const int kbyte = (ks * 8 + tg) * 4;

            uint32_t a[2][4];
            #pragma unroll
            for (int mt = 0; mt < 2; ++mt) {
                int r0 = warpM * 32 + mt * 16 + g;
                a[mt][0] = *(const uint32_t*)(As + r0 * (ROWPF * 4) + kbyte);
                a[mt][1] = *(const uint32_t*)(As + (r0 + 8) * (ROWPF * 4) + kbyte);
                a[mt][2] = *(const uint32_t*)(As + r0 * (ROWPF * 4) + kbyte + 16);
                a[mt][3] = *(const uint32_t*)(As + (r0 + 8) * (ROWPF * 4) + kbyte + 16);
            }
            uint32_t b[8][2];
            #pragma unroll
            for (int nt = 0; nt < 8; ++nt) {
                int r = warpN * 64 + nt * 8 + g;
                b[nt][0] = *(const uint32_t*)(Bs + r * (ROWPF * 4) + kbyte);
                b[nt][1] = *(const uint32_t*)(Bs + r * (ROWPF * 4) + kbyte + 16);
            }
            #pragma unroll
            for (int mt = 0; mt < 2; ++mt)
                #pragma unroll
                for (int nt = 0; nt < 8; ++nt)
                    mma_tf32(acc[mt][nt], a[mt], b[nt]);
        }
        __syncthreads();
    }

    // ---- epilogue: bias + relu, float2 stores ----
    float2 bv[8];
    #pragma unroll
    for (int nt = 0; nt < 8; ++nt) {
        int col = colBase + warpN * 64 + nt * 8 + tg * 2;
        bv[nt].x = __ldg(bias + col);
        bv[nt].y = __ldg(bias + col + 1);
    }
    #pragma unroll
    for (int mt = 0; mt < 2; ++mt) {
        #pragma unroll
        for (int half = 0; half < 2; ++half) {
            int row = rowBase + warpM * 32 + mt * 16 + g + half * 8;
            if (row >= N_DST0) continue;
            #pragma unroll
            for (int nt = 0; nt < 8; ++nt) {
                int col = colBase + warpN * 64 + nt * 8 + tg * 2;
                float2 o;
                o.x = fmaxf(acc[mt][nt][half * 2 + 0] + bv[nt].x, 0.f);
                o.y = fmaxf(acc[mt][nt][half * 2 + 1] + bv[nt].y, 0.f);
                *(float2*)(g_h + (size_t)row * HID + col) = o;
            }
        }
    }
}

// ---------------- fused layer-1 aggregation + output layer -------------------
__global__ __launch_bounds__(256)
void k_agg1_out(const float* __restrict__ Ws1,
                const float* __restrict__ Wn1,
                const float* __restrict__ b1,
                float* __restrict__ out) {
    __shared__ float hd[HID];
    __shared__ float ha[HID];
    const int dst = blockIdx.x;
    const int t   = threadIdx.x;

    const int beg = g_off1[dst];
    const int end = g_off1[dst + 1];
    float acc = 0.f;
    for (int e = beg; e < end; ++e)
        acc += g_h[(size_t)g_src1[e] * HID + t];
    const float inv = (end > beg) ? 1.0f / (float)(end - beg) : 0.0f;
    ha[t] = acc * inv;
    hd[t] = g_h[(size_t)dst * HID + t];     // h_dst1 = h[:1000]
    __syncthreads();

    if (t < NCLS) {
        float s = b1[t];
        #pragma unroll 4
        for (int k = 0; k < HID; ++k)
            s += hd[k] * Ws1[k * NCLS + t] + ha[k] * Wn1[k * NCLS + t];
        out[dst * NCLS + t] = s;
    }
}

// ---------------- launch (single stream, graph-capture safe) -----------------
extern "C" void kernel_launch(void* const* d_in, const int* in_sizes, int n_in,
                              void* d_out, int out_size) {
    const float* x      = (const float*)d_in[0];
    const float* Wself0 = (const float*)d_in[1];
    const float* Wneigh0= (const float*)d_in[2];
    const float* b0     = (const float*)d_in[3];
    const float* Wself1 = (const float*)d_in[4];
    const float* Wneigh1= (const float*)d_in[5];
    const float* b1     = (const float*)d_in[6];
    const int*   e0_src = (const int*)d_in[7];
    const int*   e0_dst = (const int*)d_in[8];
    const int*   e1_src = (const int*)d_in[9];
    const int*   e1_dst = (const int*)d_in[10];
    float* out = (float*)d_out;

    static bool attr_set = false;
    if (!attr_set) {
        cudaFuncSetAttribute(k_gemm_mma, cudaFuncAttributeMaxDynamicSharedMemorySize, GEMM_SMEM);
        attr_set = true;
    }

    k_zero          <<<(N_DST0 + 255) / 256, 256>>>();
    k_count_prepw   <<<CNT_BLKS + PW_BLKS, 256>>>(e0_dst, e1_dst, Wself0, Wneigh0);
    k_scan          <<<2, 1024>>>();
    k_scatter_prepx <<<CNT_BLKS + PX_BLKS, 256>>>(e0_src, e0_dst, e1_src, e1_dst, x);
    k_agg0          <<<N_DST0, 128>>>(x);
    k_gemm_mma      <<<dim3((N_DST0 + 127) / 128, 2), 256, GEMM_SMEM>>>(b0);
    k_agg1_out      <<<N_DST1, 256>>>(Wself1, Wneigh1, b1, out);
}

// round 12
// speedup vs baseline: 1.0763x; 1.0763x over previous
#include <cuda_runtime.h>
#include <cuda_bf16.h>
#include <cstdint>
#include <cstddef>

// Problem constants
#define N_SRC0   286000
#define N_DST0   11000
#define N_E0     275000
#define N_DST1   1000
#define N_E1     10000
#define F_IN     602
#define HID      256
#define NCLS     41
#define KPAD     608          // 19 chunks of 32
#define F2       (F_IN / 2)   // 301
#define P2       (KPAD / 2)   // 304
#define KCH      19           // K-chunks per phase

// k-group permutation: within each 8-k group store [k0,k4,k1,k5,k2,k6,k3,k7]
// so an mma thread's two k-values (tg, tg+4) are ADJACENT -> LDS.64 fragments.
__device__ __forceinline__ int kperm(int k) {
    int kk = k & 7;
    int w  = (kk < 4) ? (2 * kk) : (2 * (kk - 4) + 1);
    return (k & ~7) | w;
}

// ---------------- scratch (device globals; no runtime allocation) ----------
__device__ int g_cnt0[N_DST0];
__device__ int g_cur0[N_DST0];
__device__ int g_off0[N_DST0 + 1];
__device__ int g_src0[N_E0];
__device__ int g_cnt1[N_DST1];
__device__ int g_cur1[N_DST1];
__device__ int g_off1[N_DST1 + 1];
__device__ int g_src1[N_E1];

// tf32-rounded fp32 operand buffers, k-permuted layout (padded to KPAD)
__device__ __align__(16) float g_xt  [(size_t)N_DST0 * KPAD];
__device__ __align__(16) float g_hagg[(size_t)N_DST0 * KPAD];
__device__ __align__(16) float g_wts [256 * KPAD];              // Wself0^T  [n][k]
__device__ __align__(16) float g_wtn [256 * KPAD];              // Wneigh0^T [n][k]

__device__ float g_h[(size_t)N_DST0 * HID];

// round-to-nearest tf32 (unbiased)
__device__ __forceinline__ float tf32r(float v) {
    uint32_t o;
    asm("cvt.rna.tf32.f32 %0, %1;" : "=r"(o) : "f"(v));
    return __uint_as_float(o);
}

// ---------------- CSR build --------------------------------------------------
__global__ void k_zero() {
    int i = blockIdx.x * blockDim.x + threadIdx.x;
    if (i < N_DST0) g_cnt0[i] = 0;
    if (i < N_DST1) g_cnt1[i] = 0;
}

// fused: edge counting + weight transpose/round prep (k-permuted store)
#define CNT_BLKS  ((N_E0 + 255) / 256)           // 1075
#define PW_BLKS   ((2 * 256 * KPAD + 255) / 256) // 1216
__global__ void k_count_prepw(const int* __restrict__ e0_dst, const int* __restrict__ e1_dst,
                              const float* __restrict__ Ws, const float* __restrict__ Wn) {
    int bx = blockIdx.x;
    if (bx < CNT_BLKS) {
        int i = bx * 256 + threadIdx.x;
        if (i < N_E0) atomicAdd(&g_cnt0[e0_dst[i]], 1);
        if (i < N_E1) atomicAdd(&g_cnt1[e1_dst[i]], 1);
    } else {
        int idx = (bx - CNT_BLKS) * 256 + threadIdx.x;
        if (idx >= 2 * 256 * KPAD) return;
        int m = idx / (256 * KPAD);
        int r = idx % (256 * KPAD);
        int n = r / KPAD;
        int k = r % KPAD;
        const float* W = m ? Wn : Ws;
        float v = (k < F_IN) ? tf32r(W[(size_t)k * HID + n]) : 0.0f;
        int d = n * KPAD + kperm(k);
        if (m) g_wtn[d] = v;
        else   g_wts[d] = v;
    }
}

// scan also zeroes g_cur (it already touches every dst index)
__device__ void scan_excl(const int* cnt, int* off, int* cur, int n) {
    __shared__ int wsum[32];
    __shared__ int carry;
    const int t = threadIdx.x, lane = t & 31, w = t >> 5;
    if (t == 0) carry = 0;
    __syncthreads();
    for (int base = 0; base < n; base += 1024) {
        int i = base + t;
        int v = (i < n) ? cnt[i] : 0;
        int s = v;
        #pragma unroll
        for (int d = 1; d < 32; d <<= 1) { int u = __shfl_up_sync(~0u, s, d); if (lane >= d) s += u; }
        if (lane == 31) wsum[w] = s;
        __syncthreads();
        if (w == 0) {
            int ws = wsum[lane];
            #pragma unroll
            for (int d = 1; d < 32; d <<= 1) { int u = __shfl_up_sync(~0u, ws, d); if (lane >= d) ws += u; }
            wsum[lane] = ws;
        }
        __syncthreads();
        int woff = (w > 0) ? wsum[w - 1] : 0;
        if (i < n) { off[i] = carry + woff + s - v; cur[i] = 0; }
        __syncthreads();
        if (t == 0) carry += wsum[31];
        __syncthreads();
    }
    if (threadIdx.x == 0) off[n] = carry;
}

__global__ void k_scan() {
    if (blockIdx.x == 0) scan_excl(g_cnt0, g_off0, g_cur0, N_DST0);
    else                 scan_excl(g_cnt1, g_off1, g_cur1, N_DST1);
}

// fused: edge scatter + x round/pad prep (k-permuted store)
#define PX_BLKS ((N_DST0 * P2 + 255) / 256)   // 13063
__global__ void k_scatter_prepx(const int* __restrict__ e0_src, const int* __restrict__ e0_dst,
                                const int* __restrict__ e1_src, const int* __restrict__ e1_dst,
                                const float* __restrict__ x) {
    int bx = blockIdx.x;
    if (bx < CNT_BLKS) {
        int i = bx * 256 + threadIdx.x;
        if (i < N_E0) {
            int d = e0_dst[i];
            int p = atomicAdd(&g_cur0[d], 1);
            g_src0[g_off0[d] + p] = e0_src[i];
        }
        if (i < N_E1) {
            int d = e1_dst[i];
            int p = atomicAdd(&g_cur1[d], 1);
            g_src1[g_off1[d] + p] = e1_src[i];
        }
    } else {
        int idx = (bx - CNT_BLKS) * 256 + threadIdx.x;
        if (idx >= N_DST0 * P2) return;
        int row = idx / P2;
        int p   = idx % P2;
        float2 v = make_float2(0.f, 0.f);
        if (p < F2) v = reinterpret_cast<const float2*>(x)[(size_t)row * F2 + p];
        float* dst = g_xt + (size_t)row * KPAD;
        dst[kperm(2 * p)]     = tf32r(v.x);
        dst[kperm(2 * p + 1)] = tf32r(v.y);
    }
}

// ---------------- layer-0 mean aggregation (big gather) ----------------------
__global__ void k_agg0(const float* __restrict__ x) {
    const int dst = blockIdx.x;
    const int beg = g_off0[dst];
    const int end = g_off0[dst + 1];
    const int t   = threadIdx.x;

    float2 acc0 = make_float2(0.f, 0.f);
    float2 acc1 = make_float2(0.f, 0.f);
    float2 acc2 = make_float2(0.f, 0.f);
    const bool has3 = (t + 256) < F2;

    int e = beg;
    for (; e + 4 <= end; e += 4) {
        const float2* r0 = reinterpret_cast<const float2*>(x + (size_t)g_src0[e + 0] * F_IN);
        const float2* r1 = reinterpret_cast<const float2*>(x + (size_t)g_src0[e + 1] * F_IN);
        const float2* r2 = reinterpret_cast<const float2*>(x + (size_t)g_src0[e + 2] * F_IN);
        const float2* r3 = reinterpret_cast<const float2*>(x + (size_t)g_src0[e + 3] * F_IN);
        float2 a0 = __ldg(r0 + t),       b0 = __ldg(r1 + t),       c0 = __ldg(r2 + t),       d0 = __ldg(r3 + t);
        float2 a1 = __ldg(r0 + t + 128), b1 = __ldg(r1 + t + 128), c1 = __ldg(r2 + t + 128), d1 = __ldg(r3 + t + 128);
        acc0.x += a0.x + b0.x + c0.x + d0.x;
        acc0.y += a0.y + b0.y + c0.y + d0.y;
        acc1.x += a1.x + b1.x + c1.x + d1.x;
        acc1.y += a1.y + b1.y + c1.y + d1.y;
        if (has3) {
            float2 a2 = __ldg(r0 + t + 256), b2 = __ldg(r1 + t + 256);
            float2 c2 = __ldg(r2 + t + 256), d2 = __ldg(r3 + t + 256);
            acc2.x += a2.x + b2.x + c2.x + d2.x;
            acc2.y += a2.y + b2.y + c2.y + d2.y;
        }
    }
    for (; e < end; ++e) {
        const float2* row = reinterpret_cast<const float2*>(x + (size_t)g_src0[e] * F_IN);
        float2 v0 = __ldg(row + t);
        float2 v1 = __ldg(row + t + 128);
        acc0.x += v0.x; acc0.y += v0.y;
        acc1.x += v1.x; acc1.y += v1.y;
        if (has3) {
            float2 v2 = __ldg(row + t + 256);
            acc2.x += v2.x; acc2.y += v2.y;
        }
    }

    const float inv = (end > beg) ? 1.0f / (float)(end - beg) : 0.0f;
    float* o = g_hagg + (size_t)dst * KPAD;
    float2 accs[3] = {acc0, acc1, acc2};
    #pragma unroll
    for (int j = 0; j < 3; ++j) {
        int p = t + j * 128;
        if (p >= P2) break;
        float vx = (p < F2) ? tf32r(accs[j].x * inv) : 0.f;
        float vy = (p < F2) ? tf32r(accs[j].y * inv) : 0.f;
        o[kperm(2 * p)]     = vx;
        o[kperm(2 * p + 1)] = vy;
    }
}

// ---------------- tensor-core GEMM via mma.sync (TF32, sm_80+ PTX) ----------
// h = relu([Xd | Hagg] @ [Ws; Wn] + b0).
// CTA tile 128x64; grid (86, 4); 8 warps = 4(M) x 2(N); warp tile 32x32.
// 2-stage cp.async pipeline, 38 flattened chunks, k-permuted operands so
// every fragment load is one conflict-free LDS.64 (ROWPF=40: 8g+2tg banks).
#define BK        32
#define ROWPF     40                       // padded row length (floats); 40%32=8 -> LDS.64 conflict-free
#define A_T       (128 * ROWPF * 4)        // 20480 B
#define B_T       (64 * ROWPF * 4)         // 10240 B
#define BUF_SZ    (A_T + B_T)              // 30720 B
#define GEMM_SMEM (2 * BUF_SZ)             // 61440 B
#define NCH       (2 * KCH)                // 38

#define CP16(dst, src, pred) \
    asm volatile("cp.async.cg.shared.global [%0], [%1], 16, %2;" \
                 :: "r"(dst), "l"(src), "r"(pred))
#define CP_COMMIT() asm volatile("cp.async.commit_group;" ::: "memory")
#define CP_WAIT(n)  asm volatile("cp.async.wait_group %0;" :: "n"(n) : "memory")

__device__ __forceinline__ uint32_t smem_u32(const void* p) {
    uint32_t a;
    asm("{ .reg .u64 t; cvta.to.shared.u64 t, %1; cvt.u32.u64 %0, t; }" : "=r"(a) : "l"(p));
    return a;
}

__device__ __forceinline__ void mma_tf32(float* d,
                                         const uint32_t* a, const uint32_t* b) {
    asm volatile(
        "mma.sync.aligned.m16n8k8.row.col.f32.tf32.tf32.f32 "
        "{%0,%1,%2,%3}, {%4,%5,%6,%7}, {%8,%9}, {%0,%1,%2,%3};"
        : "+f"(d[0]), "+f"(d[1]), "+f"(d[2]), "+f"(d[3])
        : "r"(a[0]), "r"(a[1]), "r"(a[2]), "r"(a[3]), "r"(b[0]), "r"(b[1]));
}

__global__ __launch_bounds__(256, 3)
void k_gemm_mma(const float* __restrict__ bias) {
    extern __shared__ char smem[];
    const uint32_t sb = smem_u32(smem);
    const int tid  = threadIdx.x;
    const int lane = tid & 31;
    const int wid  = tid >> 5;
    const int warpM = wid & 3;            // 0..3
    const int warpN = wid >> 2;           // 0..1
    const int g  = lane >> 2;             // 0..7
    const int tg = lane & 3;              // 0..3
    const int rowBase = blockIdx.x * 128;
    const int colBase = blockIdx.y * 64;

    auto issue = [&](int c) {
        const int ph = (c >= KCH);
        const int kb = (c - ph * KCH) * BK;
        const float* A = ph ? g_hagg : g_xt;
        const float* B = ph ? g_wtn : g_wts;
        const uint32_t bufb = sb + (uint32_t)(c & 1) * BUF_SZ;

        // A: 128 rows x 32 floats = 1024 vec16 -> 4 per thread
        #pragma unroll
        for (int u = 0; u < 4; ++u) {
            int idx = tid + u * 256;          // 0..1023
            int row = idx >> 3, v = idx & 7;
            int grow = rowBase + row;
            int pr = (grow < N_DST0) ? 16 : 0;
            size_t gb = ((size_t)grow * KPAD + kb + v * 4) * 4;
            if (grow >= N_DST0) gb = 0;
            uint32_t so = bufb + (uint32_t)(row * (ROWPF * 4) + v * 16);
            CP16(so, (const char*)A + gb, pr);
        }
        // B: 64 rows x 32 floats = 512 vec16 -> 2 per thread
        #pragma unroll
        for (int u = 0; u < 2; ++u) {
            int idx = tid + u * 256;          // 0..511
            int row = idx >> 3, v = idx & 7;
            size_t gb = ((size_t)(colBase + row) * KPAD + kb + v * 4) * 4;
            uint32_t so = bufb + (uint32_t)(A_T + row * (ROWPF * 4) + v * 16);
            CP16(so, (const char*)B + gb, 16);
        }
    };

    float acc[2][4][4] = {};   // [mtile][ntile][reg]

    issue(0);
    CP_COMMIT();

    for (int c = 0; c < NCH; ++c) {
        if (c + 1 < NCH) { issue(c + 1); CP_COMMIT(); CP_WAIT(1); }
        else             { CP_WAIT(0); }
        __syncthreads();

        const char* buf = smem + (c & 1) * BUF_SZ;
        const char* As = buf;
        const char* Bs = buf + A_T;

        #pragma unroll
        for (int ks = 0; ks < 4; ++ks) {
            const int koff = (ks * 8 + 2 * tg) * 4;   // permuted: (k=tg, k=tg+4) adjacent

            uint32_t a[2][4];
            #pragma unroll
            for (int mt = 0; mt < 2; ++mt) {
                int r0 = warpM * 32 + mt * 16 + g;
                uint2 lo = *(const uint2*)(As + r0 * (ROWPF * 4) + koff);
                uint2 hi = *(const uint2*)(As + (r0 + 8) * (ROWPF * 4) + koff);
                a[mt][0] = lo.x;   // A[r0,   tg]
                a[mt][1] = hi.x;   // A[r0+8, tg]
                a[mt][2] = lo.y;   // A[r0,   tg+4]
                a[mt][3] = hi.y;   // A[r0+8, tg+4]
            }
            uint32_t b[4][2];
            #pragma unroll
            for (int nt = 0; nt < 4; ++nt) {
                int r = warpN * 32 + nt * 8 + g;
                uint2 bb = *(const uint2*)(Bs + r * (ROWPF * 4) + koff);
                b[nt][0] = bb.x;   // B[n, tg]
                b[nt][1] = bb.y;   // B[n, tg+4]
            }
            #pragma unroll
            for (int mt = 0; mt < 2; ++mt)
                #pragma unroll
                for (int nt = 0; nt < 4; ++nt)
                    mma_tf32(acc[mt][nt], a[mt], b[nt]);
        }
        __syncthreads();
    }

    // ---- epilogue: bias + relu, float2 stores ----
    float2 bv[4];
    #pragma unroll
    for (int nt = 0; nt < 4; ++nt) {
        int col = colBase + warpN * 32 + nt * 8 + tg * 2;
        bv[nt].x = __ldg(bias + col);
        bv[nt].y = __ldg(bias + col + 1);
    }
    #pragma unroll
    for (int mt = 0; mt < 2; ++mt) {
        #pragma unroll
        for (int half = 0; half < 2; ++half) {
            int row = rowBase + warpM * 32 + mt * 16 + g + half * 8;
            if (row >= N_DST0) continue;
            #pragma unroll
            for (int nt = 0; nt < 4; ++nt) {
                int col = colBase + warpN * 32 + nt * 8 + tg * 2;
                float2 o;
                o.x = fmaxf(acc[mt][nt][half * 2 + 0] + bv[nt].x, 0.f);
                o.y = fmaxf(acc[mt][nt][half * 2 + 1] + bv[nt].y, 0.f);
                *(float2*)(g_h + (size_t)row * HID + col) = o;
            }
        }
    }
}

// ---------------- fused layer-1 aggregation + output layer -------------------
__global__ __launch_bounds__(256)
void k_agg1_out(const float* __restrict__ Ws1,
                const float* __restrict__ Wn1,
                const float* __restrict__ b1,
                float* __restrict__ out) {
    __shared__ float hd[HID];
    __shared__ float ha[HID];
    const int dst = blockIdx.x;
    const int t   = threadIdx.x;

    const int beg = g_off1[dst];
    const int end = g_off1[dst + 1];
    float acc = 0.f;
    for (int e = beg; e < end; ++e)
        acc += g_h[(size_t)g_src1[e] * HID + t];
    const float inv = (end > beg) ? 1.0f / (float)(end - beg) : 0.0f;
    ha[t] = acc * inv;
    hd[t] = g_h[(size_t)dst * HID + t];     // h_dst1 = h[:1000]
    __syncthreads();

    if (t < NCLS) {
        float s = b1[t];
        #pragma unroll 4
        for (int k = 0; k < HID; ++k)
            s += hd[k] * Ws1[k * NCLS + t] + ha[k] * Wn1[k * NCLS + t];
        out[dst * NCLS + t] = s;
    }
}

// ---------------- launch (single stream, graph-capture safe) -----------------
extern "C" void kernel_launch(void* const* d_in, const int* in_sizes, int n_in,
                              void* d_out, int out_size) {
    const float* x      = (const float*)d_in[0];
    const float* Wself0 = (const float*)d_in[1];
    const float* Wneigh0= (const float*)d_in[2];
    const float* b0     = (const float*)d_in[3];
    const float* Wself1 = (const float*)d_in[4];
    const float* Wneigh1= (const float*)d_in[5];
    const float* b1     = (const float*)d_in[6];
    const int*   e0_src = (const int*)d_in[7];
    const int*   e0_dst = (const int*)d_in[8];
    const int*   e1_src = (const int*)d_in[9];
    const int*   e1_dst = (const int*)d_in[10];
    float* out = (float*)d_out;

    static bool attr_set = false;
    if (!attr_set) {
        cudaFuncSetAttribute(k_gemm_mma, cudaFuncAttributeMaxDynamicSharedMemorySize, GEMM_SMEM);
        attr_set = true;
    }

    k_zero          <<<(N_DST0 + 255) / 256, 256>>>();
    k_count_prepw   <<<CNT_BLKS + PW_BLKS, 256>>>(e0_dst, e1_dst, Wself0, Wneigh0);
    k_scan          <<<2, 1024>>>();
    k_scatter_prepx <<<CNT_BLKS + PX_BLKS, 256>>>(e0_src, e0_dst, e1_src, e1_dst, x);
    k_agg0          <<<N_DST0, 128>>>(x);
    k_gemm_mma      <<<dim3((N_DST0 + 127) / 128, 4), 256, GEMM_SMEM>>>(b0);
    k_agg1_out      <<<N_DST1, 256>>>(Wself1, Wneigh1, b1, out);
}

// round 13
// speedup vs baseline: 1.2386x; 1.1508x over previous
#include <cuda_runtime.h>
#include <cuda_fp16.h>
#include <cstdint>
#include <cstddef>

// Problem constants
#define N_SRC0   286000
#define N_DST0   11000
#define N_E0     275000
#define N_DST1   1000
#define N_E1     10000
#define F_IN     602
#define HID      256
#define NCLS     41
#define KPAD     640          // 10 chunks of 64 (fp16 path)
#define F2       (F_IN / 2)   // 301
#define P2       (KPAD / 2)   // 320
#define KCH      10           // K64-chunks per phase

// k-permutation within each 16-k group: [k0k1 k8k9 | k2k3 k10k11 | k4k5 k12k13 | k6k7 k14k15]
// -> thread(g,tg)'s fragment halves (k=2tg,2tg+1,2tg+8,2tg+9) are one contiguous 8B unit.
__device__ __forceinline__ int hperm(int k) {
    int kk = k & 15;
    int p = kk >> 1, b = kk & 1;
    int o = (p < 4) ? (p * 4 + b) : ((p - 4) * 4 + 2 + b);
    return (k & ~15) | o;
}

// ---------------- scratch (device globals; no runtime allocation) ----------
__device__ int g_cnt0[N_DST0];
__device__ int g_cur0[N_DST0];
__device__ int g_off0[N_DST0 + 1];
__device__ int g_src0[N_E0];
__device__ int g_cnt1[N_DST1];
__device__ int g_cur1[N_DST1];
__device__ int g_off1[N_DST1 + 1];
__device__ int g_src1[N_E1];

// fp16 operand buffers, k-permuted layout (padded to KPAD)
__device__ __align__(16) __half g_xt  [(size_t)N_DST0 * KPAD];
__device__ __align__(16) __half g_hagg[(size_t)N_DST0 * KPAD];
__device__ __align__(16) __half g_wts [256 * KPAD];              // Wself0^T  [n][k]
__device__ __align__(16) __half g_wtn [256 * KPAD];              // Wneigh0^T [n][k]

__device__ float g_h[(size_t)N_DST0 * HID];

// ---------------- CSR build --------------------------------------------------
__global__ void k_zero() {
    int i = blockIdx.x * blockDim.x + threadIdx.x;
    if (i < N_DST0) g_cnt0[i] = 0;
    if (i < N_DST1) g_cnt1[i] = 0;
}

// fused: edge counting + weight transpose/round prep (k-permuted fp16 store)
#define CNT_BLKS  ((N_E0 + 255) / 256)           // 1075
#define PW_BLKS   ((2 * 256 * KPAD + 255) / 256) // 1280
__global__ void k_count_prepw(const int* __restrict__ e0_dst, const int* __restrict__ e1_dst,
                              const float* __restrict__ Ws, const float* __restrict__ Wn) {
    int bx = blockIdx.x;
    if (bx < CNT_BLKS) {
        int i = bx * 256 + threadIdx.x;
        if (i < N_E0) atomicAdd(&g_cnt0[e0_dst[i]], 1);
        if (i < N_E1) atomicAdd(&g_cnt1[e1_dst[i]], 1);
    } else {
        int idx = (bx - CNT_BLKS) * 256 + threadIdx.x;
        if (idx >= 2 * 256 * KPAD) return;
        int m = idx / (256 * KPAD);
        int r = idx % (256 * KPAD);
        int n = r / KPAD;
        int k = r % KPAD;
        const float* W = m ? Wn : Ws;
        float v = (k < F_IN) ? W[(size_t)k * HID + n] : 0.0f;
        __half h = __float2half_rn(v);
        int d = n * KPAD + hperm(k);
        if (m) g_wtn[d] = h;
        else   g_wts[d] = h;
    }
}

// scan also zeroes g_cur
__device__ void scan_excl(const int* cnt, int* off, int* cur, int n) {
    __shared__ int wsum[32];
    __shared__ int carry;
    const int t = threadIdx.x, lane = t & 31, w = t >> 5;
    if (t == 0) carry = 0;
    __syncthreads();
    for (int base = 0; base < n; base += 1024) {
        int i = base + t;
        int v = (i < n) ? cnt[i] : 0;
        int s = v;
        #pragma unroll
        for (int d = 1; d < 32; d <<= 1) { int u = __shfl_up_sync(~0u, s, d); if (lane >= d) s += u; }
        if (lane == 31) wsum[w] = s;
        __syncthreads();
        if (w == 0) {
            int ws = wsum[lane];
            #pragma unroll
            for (int d = 1; d < 32; d <<= 1) { int u = __shfl_up_sync(~0u, ws, d); if (lane >= d) ws += u; }
            wsum[lane] = ws;
        }
        __syncthreads();
        int woff = (w > 0) ? wsum[w - 1] : 0;
        if (i < n) { off[i] = carry + woff + s - v; cur[i] = 0; }
        __syncthreads();
        if (t == 0) carry += wsum[31];
        __syncthreads();
    }
    if (threadIdx.x == 0) off[n] = carry;
}

__global__ void k_scan() {
    if (blockIdx.x == 0) scan_excl(g_cnt0, g_off0, g_cur0, N_DST0);
    else                 scan_excl(g_cnt1, g_off1, g_cur1, N_DST1);
}

// fused: edge scatter + x fp16 prep (k-permuted half2 store)
#define PX_BLKS ((N_DST0 * P2 + 255) / 256)   // 13750
__global__ void k_scatter_prepx(const int* __restrict__ e0_src, const int* __restrict__ e0_dst,
                                const int* __restrict__ e1_src, const int* __restrict__ e1_dst,
                                const float* __restrict__ x) {
    int bx = blockIdx.x;
    if (bx < CNT_BLKS) {
        int i = bx * 256 + threadIdx.x;
        if (i < N_E0) {
            int d = e0_dst[i];
            int p = atomicAdd(&g_cur0[d], 1);
            g_src0[g_off0[d] + p] = e0_src[i];
        }
        if (i < N_E1) {
            int d = e1_dst[i];
            int p = atomicAdd(&g_cur1[d], 1);
            g_src1[g_off1[d] + p] = e1_src[i];
        }
    } else {
        int idx = (bx - CNT_BLKS) * 256 + threadIdx.x;
        if (idx >= N_DST0 * P2) return;
        int row = idx / P2;
        int p   = idx % P2;
        float2 v = make_float2(0.f, 0.f);
        if (p < F2) v = reinterpret_cast<const float2*>(x)[(size_t)row * F2 + p];
        // k=2p,2p+1 map to adjacent permuted slots (same pair) -> half2 store
        __half* dst = g_xt + (size_t)row * KPAD;
        *reinterpret_cast<half2*>(dst + hperm(2 * p)) = __floats2half2_rn(v.x, v.y);
    }
}

// ---------------- layer-0 mean aggregation (big gather) ----------------------
__global__ void k_agg0(const float* __restrict__ x) {
    const int dst = blockIdx.x;
    const int beg = g_off0[dst];
    const int end = g_off0[dst + 1];
    const int t   = threadIdx.x;

    float2 acc0 = make_float2(0.f, 0.f);
    float2 acc1 = make_float2(0.f, 0.f);
    float2 acc2 = make_float2(0.f, 0.f);
    const bool has3 = (t + 256) < F2;

    int e = beg;
    for (; e + 4 <= end; e += 4) {
        const float2* r0 = reinterpret_cast<const float2*>(x + (size_t)g_src0[e + 0] * F_IN);
        const float2* r1 = reinterpret_cast<const float2*>(x + (size_t)g_src0[e + 1] * F_IN);
        const float2* r2 = reinterpret_cast<const float2*>(x + (size_t)g_src0[e + 2] * F_IN);
        const float2* r3 = reinterpret_cast<const float2*>(x + (size_t)g_src0[e + 3] * F_IN);
        float2 a0 = __ldg(r0 + t),       b0 = __ldg(r1 + t),       c0 = __ldg(r2 + t),       d0 = __ldg(r3 + t);
        float2 a1 = __ldg(r0 + t + 128), b1 = __ldg(r1 + t + 128), c1 = __ldg(r2 + t + 128), d1 = __ldg(r3 + t + 128);
        acc0.x += a0.x + b0.x + c0.x + d0.x;
        acc0.y += a0.y + b0.y + c0.y + d0.y;
        acc1.x += a1.x + b1.x + c1.x + d1.x;
        acc1.y += a1.y + b1.y + c1.y + d1.y;
        if (has3) {
            float2 a2 = __ldg(r0 + t + 256), b2 = __ldg(r1 + t + 256);
            float2 c2 = __ldg(r2 + t + 256), d2 = __ldg(r3 + t + 256);
            acc2.x += a2.x + b2.x + c2.x + d2.x;
            acc2.y += a2.y + b2.y + c2.y + d2.y;
        }
    }
    for (; e < end; ++e) {
        const float2* row = reinterpret_cast<const float2*>(x + (size_t)g_src0[e] * F_IN);
        float2 v0 = __ldg(row + t);
        float2 v1 = __ldg(row + t + 128);
        acc0.x += v0.x; acc0.y += v0.y;
        acc1.x += v1.x; acc1.y += v1.y;
        if (has3) {
            float2 v2 = __ldg(row + t + 256);
            acc2.x += v2.x; acc2.y += v2.y;
        }
    }

    const float inv = (end > beg) ? 1.0f / (float)(end - beg) : 0.0f;
    __half* o = g_hagg + (size_t)dst * KPAD;
    float2 accs[3] = {acc0, acc1, acc2};
    #pragma unroll
    for (int j = 0; j < 3; ++j) {
        int p = t + j * 128;
        if (p >= P2) break;
        float vx = (p < F2) ? accs[j].x * inv : 0.f;
        float vy = (p < F2) ? accs[j].y * inv : 0.f;
        *reinterpret_cast<half2*>(o + hperm(2 * p)) = __floats2half2_rn(vx, vy);
    }
}

// ---------------- tensor-core GEMM via mma.sync (FP16, sm_80+ PTX) ----------
// h = relu([Xd | Hagg] @ [Ws; Wn] + b0), fp16 operands (10-bit mantissa = tf32),
// fp32 accumulate. CTA tile 128x64; grid (86, 4); 8 warps = 4(M) x 2(N);
// warp tile 32x32; m16n8k16; BK=64; 20 flattened chunks, 2-stage cp.async.
// k-permuted operands: every fragment load is one LDS.64; ROWPH=80 halves
// (160 B = 40 words ≡ 8 mod 32) -> half-warp conflict-free 64-bit loads.
#define BK        64
#define ROWPH     80                       // padded row length (halves)
#define ROWB      (ROWPH * 2)              // 160 B
#define A_T       (128 * ROWB)             // 20480 B
#define B_T       (64 * ROWB)              // 10240 B
#define BUF_SZ    (A_T + B_T)              // 30720 B
#define GEMM_SMEM (2 * BUF_SZ)             // 61440 B
#define NCH       (2 * KCH)                // 20

#define CP16(dst, src, pred) \
    asm volatile("cp.async.cg.shared.global [%0], [%1], 16, %2;" \
                 :: "r"(dst), "l"(src), "r"(pred))
#define CP_COMMIT() asm volatile("cp.async.commit_group;" ::: "memory")
#define CP_WAIT(n)  asm volatile("cp.async.wait_group %0;" :: "n"(n) : "memory")

__device__ __forceinline__ uint32_t smem_u32(const void* p) {
    uint32_t a;
    asm("{ .reg .u64 t; cvta.to.shared.u64 t, %1; cvt.u32.u64 %0, t; }" : "=r"(a) : "l"(p));
    return a;
}

__device__ __forceinline__ void mma_f16(float* d,
                                        const uint32_t* a, const uint32_t* b) {
    asm volatile(
        "mma.sync.aligned.m16n8k16.row.col.f32.f16.f16.f32 "
        "{%0,%1,%2,%3}, {%4,%5,%6,%7}, {%8,%9}, {%0,%1,%2,%3};"
        : "+f"(d[0]), "+f"(d[1]), "+f"(d[2]), "+f"(d[3])
        : "r"(a[0]), "r"(a[1]), "r"(a[2]), "r"(a[3]), "r"(b[0]), "r"(b[1]));
}

__global__ __launch_bounds__(256, 3)
void k_gemm_mma(const float* __restrict__ bias) {
    extern __shared__ char smem[];
    const uint32_t sb = smem_u32(smem);
    const int tid  = threadIdx.x;
    const int lane = tid & 31;
    const int wid  = tid >> 5;
    const int warpM = wid & 3;            // 0..3
    const int warpN = wid >> 2;           // 0..1
    const int g  = lane >> 2;             // 0..7
    const int tg = lane & 3;              // 0..3
    const int rowBase = blockIdx.x * 128;
    const int colBase = blockIdx.y * 64;

    auto issue = [&](int c) {
        const int ph = (c >= KCH);
        const int kb = (c - ph * KCH) * BK;            // half-index
        const __half* A = ph ? g_hagg : g_xt;
        const __half* B = ph ? g_wtn : g_wts;
        const uint32_t bufb = sb + (uint32_t)(c & 1) * BUF_SZ;

        // A: 128 rows x 64 halves (128 B) = 1024 vec16 -> 4 per thread
        #pragma unroll
        for (int u = 0; u < 4; ++u) {
            int idx = tid + u * 256;          // 0..1023
            int row = idx >> 3, v = idx & 7;
            int grow = rowBase + row;
            int pr = (grow < N_DST0) ? 16 : 0;
            size_t gb = ((size_t)grow * KPAD + kb) * 2 + v * 16;
            if (grow >= N_DST0) gb = 0;
            uint32_t so = bufb + (uint32_t)(row * ROWB + v * 16);
            CP16(so, (const char*)A + gb, pr);
        }
        // B: 64 rows x 64 halves = 512 vec16 -> 2 per thread
        #pragma unroll
        for (int u = 0; u < 2; ++u) {
            int idx = tid + u * 256;          // 0..511
            int row = idx >> 3, v = idx & 7;
            size_t gb = ((size_t)(colBase + row) * KPAD + kb) * 2 + v * 16;
            uint32_t so = bufb + (uint32_t)(A_T + row * ROWB + v * 16);
            CP16(so, (const char*)B + gb, 16);
        }
    };

    float acc[2][4][4] = {};   // [mtile][ntile][reg]

    issue(0);
    CP_COMMIT();

    for (int c = 0; c < NCH; ++c) {
        if (c + 1 < NCH) { issue(c + 1); CP_COMMIT(); CP_WAIT(1); }
        else             { CP_WAIT(0); }
        __syncthreads();

        const char* buf = smem + (c & 1) * BUF_SZ;
        const char* As = buf;
        const char* Bs = buf + A_T;

        #pragma unroll
        for (int ks = 0; ks < 4; ++ks) {                 // 4 k16 steps per BK=64
            const int koff = ks * 32 + tg * 8;           // permuted 8B group

            uint32_t a[2][4];
            #pragma unroll
            for (int mt = 0; mt < 2; ++mt) {
                int r0 = warpM * 32 + mt * 16 + g;
                uint2 lo = *(const uint2*)(As + r0 * ROWB + koff);        // A[r0]:   (k2tg,k2tg+1),(k2tg+8,k2tg+9)
                uint2 hi = *(const uint2*)(As + (r0 + 8) * ROWB + koff);  // A[r0+8]
                a[mt][0] = lo.x;
                a[mt][1] = hi.x;
                a[mt][2] = lo.y;
                a[mt][3] = hi.y;
            }
            uint32_t b[4][2];
            #pragma unroll
            for (int nt = 0; nt < 4; ++nt) {
                int r = warpN * 32 + nt * 8 + g;
                uint2 bb = *(const uint2*)(Bs + r * ROWB + koff);
                b[nt][0] = bb.x;
                b[nt][1] = bb.y;
            }
            #pragma unroll
            for (int mt = 0; mt < 2; ++mt)
                #pragma unroll
                for (int nt = 0; nt < 4; ++nt)
                    mma_f16(acc[mt][nt], a[mt], b[nt]);
        }
        __syncthreads();
    }

    // ---- epilogue: bias + relu, float2 stores ----
    float2 bv[4];
    #pragma unroll
    for (int nt = 0; nt < 4; ++nt) {
        int col = colBase + warpN * 32 + nt * 8 + tg * 2;
        bv[nt].x = __ldg(bias + col);
        bv[nt].y = __ldg(bias + col + 1);
    }
    #pragma unroll
    for (int mt = 0; mt < 2; ++mt) {
        #pragma unroll
        for (int half = 0; half < 2; ++half) {
            int row = rowBase + warpM * 32 + mt * 16 + g + half * 8;
            if (row >= N_DST0) continue;
            #pragma unroll
            for (int nt = 0; nt < 4; ++nt) {
                int col = colBase + warpN * 32 + nt * 8 + tg * 2;
                float2 o;
                o.x = fmaxf(acc[mt][nt][half * 2 + 0] + bv[nt].x, 0.f);
                o.y = fmaxf(acc[mt][nt][half * 2 + 1] + bv[nt].y, 0.f);
                *(float2*)(g_h + (size_t)row * HID + col) = o;
            }
        }
    }
}

// ---------------- fused layer-1 aggregation + output layer -------------------
__global__ __launch_bounds__(256)
void k_agg1_out(const float* __restrict__ Ws1,
                const float* __restrict__ Wn1,
                const float* __restrict__ b1,
                float* __restrict__ out) {
    __shared__ float hd[HID];
    __shared__ float ha[HID];
    const int dst = blockIdx.x;
    const int t   = threadIdx.x;

    const int beg = g_off1[dst];
    const int end = g_off1[dst + 1];
    float acc = 0.f;
    for (int e = beg; e < end; ++e)
        acc += g_h[(size_t)g_src1[e] * HID + t];
    const float inv = (end > beg) ? 1.0f / (float)(end - beg) : 0.0f;
    ha[t] = acc * inv;
    hd[t] = g_h[(size_t)dst * HID + t];     // h_dst1 = h[:1000]
    __syncthreads();

    if (t < NCLS) {
        float s = b1[t];
        #pragma unroll 4
        for (int k = 0; k < HID; ++k)
            s += hd[k] * Ws1[k * NCLS + t] + ha[k] * Wn1[k * NCLS + t];
        out[dst * NCLS + t] = s;
    }
}

// ---------------- launch (single stream, graph-capture safe) -----------------
extern "C" void kernel_launch(void* const* d_in, const int* in_sizes, int n_in,
                              void* d_out, int out_size) {
    const float* x      = (const float*)d_in[0];
    const float* Wself0 = (const float*)d_in[1];
    const float* Wneigh0= (const float*)d_in[2];
    const float* b0     = (const float*)d_in[3];
    const float* Wself1 = (const float*)d_in[4];
    const float* Wneigh1= (const float*)d_in[5];
    const float* b1     = (const float*)d_in[6];
    const int*   e0_src = (const int*)d_in[7];
    const int*   e0_dst = (const int*)d_in[8];
    const int*   e1_src = (const int*)d_in[9];
    const int*   e1_dst = (const int*)d_in[10];
    float* out = (float*)d_out;

    static bool attr_set = false;
    if (!attr_set) {
        cudaFuncSetAttribute(k_gemm_mma, cudaFuncAttributeMaxDynamicSharedMemorySize, GEMM_SMEM);
        attr_set = true;
    }

    k_zero          <<<(N_DST0 + 255) / 256, 256>>>();
    k_count_prepw   <<<CNT_BLKS + PW_BLKS, 256>>>(e0_dst, e1_dst, Wself0, Wneigh0);
    k_scan          <<<2, 1024>>>();
    k_scatter_prepx <<<CNT_BLKS + PX_BLKS, 256>>>(e0_src, e0_dst, e1_src, e1_dst, x);
    k_agg0          <<<N_DST0, 128>>>(x);
    k_gemm_mma      <<<dim3((N_DST0 + 127) / 128, 4), 256, GEMM_SMEM>>>(b0);
    k_agg1_out      <<<N_DST1, 256>>>(Wself1, Wneigh1, b1, out);
}

// round 14
// speedup vs baseline: 1.3261x; 1.0706x over previous
#include <cuda_runtime.h>
#include <cuda_fp16.h>
#include <cstdint>
#include <cstddef>

// Problem constants
#define N_SRC0   286000
#define N_DST0   11000
#define N_E0     275000
#define N_DST1   1000
#define N_E1     10000
#define F_IN     602
#define HID      256
#define NCLS     41
#define KPAD     640          // 10 chunks of 64 (fp16 path)
#define F2       (F_IN / 2)   // 301
#define P2       (KPAD / 2)   // 320
#define KCH      10           // K64-chunks per phase

// k-permutation within each 16-k group: [k0k1 k8k9 | k2k3 k10k11 | k4k5 k12k13 | k6k7 k14k15]
__device__ __forceinline__ int hperm(int k) {
    int kk = k & 15;
    int p = kk >> 1, b = kk & 1;
    int o = (p < 4) ? (p * 4 + b) : ((p - 4) * 4 + 2 + b);
    return (k & ~15) | o;
}

// ---------------- scratch (device globals; no runtime allocation) ----------
__device__ int g_cnt0[N_DST0];
__device__ int g_cur0[N_DST0];
__device__ int g_off0[N_DST0 + 1];
__device__ int g_src0[N_E0];
__device__ int g_cnt1[N_DST1];
__device__ int g_cur1[N_DST1];
__device__ int g_off1[N_DST1 + 1];
__device__ int g_src1[N_E1];

// fp16 operand buffers, k-permuted layout (padded to KPAD)
__device__ __align__(16) __half g_xt  [(size_t)N_DST0 * KPAD];
__device__ __align__(16) __half g_hagg[(size_t)N_DST0 * KPAD];
__device__ __align__(16) __half g_wts [256 * KPAD];              // Wself0^T  [n][k]
__device__ __align__(16) __half g_wtn [256 * KPAD];              // Wneigh0^T [n][k]

__device__ float g_h[(size_t)N_DST0 * HID];

// ---------------- CSR build --------------------------------------------------
__global__ void k_zero() {
    int i = blockIdx.x * blockDim.x + threadIdx.x;
    if (i < N_DST0) g_cnt0[i] = 0;
    if (i < N_DST1) g_cnt1[i] = 0;
}

__global__ void k_count(const int* __restrict__ e0_dst, const int* __restrict__ e1_dst) {
    int i = blockIdx.x * blockDim.x + threadIdx.x;
    if (i < N_E0) atomicAdd(&g_cnt0[e0_dst[i]], 1);
    if (i < N_E1) atomicAdd(&g_cnt1[e1_dst[i]], 1);
}

// scan also zeroes g_cur
__device__ void scan_excl(const int* cnt, int* off, int* cur, int n) {
    __shared__ int wsum[32];
    __shared__ int carry;
    const int t = threadIdx.x, lane = t & 31, w = t >> 5;
    if (t == 0) carry = 0;
    __syncthreads();
    for (int base = 0; base < n; base += 1024) {
        int i = base + t;
        int v = (i < n) ? cnt[i] : 0;
        int s = v;
        #pragma unroll
        for (int d = 1; d < 32; d <<= 1) { int u = __shfl_up_sync(~0u, s, d); if (lane >= d) s += u; }
        if (lane == 31) wsum[w] = s;
        __syncthreads();
        if (w == 0) {
            int ws = wsum[lane];
            #pragma unroll
            for (int d = 1; d < 32; d <<= 1) { int u = __shfl_up_sync(~0u, ws, d); if (lane >= d) ws += u; }
            wsum[lane] = ws;
        }
        __syncthreads();
        int woff = (w > 0) ? wsum[w - 1] : 0;
        if (i < n) { off[i] = carry + woff + s - v; cur[i] = 0; }
        __syncthreads();
        if (t == 0) carry += wsum[31];
        __syncthreads();
    }
    if (threadIdx.x == 0) off[n] = carry;
}

__global__ void k_scan() {
    if (blockIdx.x == 0) scan_excl(g_cnt0, g_off0, g_cur0, N_DST0);
    else                 scan_excl(g_cnt1, g_off1, g_cur1, N_DST1);
}

__global__ void k_scatter(const int* __restrict__ e0_src, const int* __restrict__ e0_dst,
                          const int* __restrict__ e1_src, const int* __restrict__ e1_dst) {
    int i = blockIdx.x * blockDim.x + threadIdx.x;
    if (i < N_E0) {
        int d = e0_dst[i];
        int p = atomicAdd(&g_cur0[d], 1);
        g_src0[g_off0[d] + p] = e0_src[i];
    }
    if (i < N_E1) {
        int d = e1_dst[i];
        int p = atomicAdd(&g_cur1[d], 1);
        g_src1[g_off1[d] + p] = e1_src[i];
    }
}

// ---------------- mega kernel: agg0 (first) + prepx + prepw filler ----------
// All blocks 128 threads, 0 smem: resource-homogeneous so the prep blocks
// stream through leftover slots while agg0 saturates DRAM.
#define PX2_BLKS ((N_DST0 * P2 + 255) / 256)     // 13750 (256 elems/block)
#define PW2_BLKS ((2 * 256 * KPAD + 255) / 256)  // 1280
#define MEGA_BLKS (N_DST0 + PX2_BLKS + PW2_BLKS)

__device__ __forceinline__ void agg0_body(int dst, const float* __restrict__ x) {
    const int beg = g_off0[dst];
    const int end = g_off0[dst + 1];
    const int t   = threadIdx.x;

    float2 acc0 = make_float2(0.f, 0.f);
    float2 acc1 = make_float2(0.f, 0.f);
    float2 acc2 = make_float2(0.f, 0.f);
    const bool has3 = (t + 256) < F2;

    int e = beg;
    for (; e + 4 <= end; e += 4) {
        const float2* r0 = reinterpret_cast<const float2*>(x + (size_t)g_src0[e + 0] * F_IN);
        const float2* r1 = reinterpret_cast<const float2*>(x + (size_t)g_src0[e + 1] * F_IN);
        const float2* r2 = reinterpret_cast<const float2*>(x + (size_t)g_src0[e + 2] * F_IN);
        const float2* r3 = reinterpret_cast<const float2*>(x + (size_t)g_src0[e + 3] * F_IN);
        float2 a0 = __ldg(r0 + t),       b0 = __ldg(r1 + t),       c0 = __ldg(r2 + t),       d0 = __ldg(r3 + t);
        float2 a1 = __ldg(r0 + t + 128), b1 = __ldg(r1 + t + 128), c1 = __ldg(r2 + t + 128), d1 = __ldg(r3 + t + 128);
        acc0.x += a0.x + b0.x + c0.x + d0.x;
        acc0.y += a0.y + b0.y + c0.y + d0.y;
        acc1.x += a1.x + b1.x + c1.x + d1.x;
        acc1.y += a1.y + b1.y + c1.y + d1.y;
        if (has3) {
            float2 a2 = __ldg(r0 + t + 256), b2 = __ldg(r1 + t + 256);
            float2 c2 = __ldg(r2 + t + 256), d2 = __ldg(r3 + t + 256);
            acc2.x += a2.x + b2.x + c2.x + d2.x;
            acc2.y += a2.y + b2.y + c2.y + d2.y;
        }
    }
    for (; e < end; ++e) {
        const float2* row = reinterpret_cast<const float2*>(x + (size_t)g_src0[e] * F_IN);
        float2 v0 = __ldg(row + t);
        float2 v1 = __ldg(row + t + 128);
        acc0.x += v0.x; acc0.y += v0.y;
        acc1.x += v1.x; acc1.y += v1.y;
        if (has3) {
            float2 v2 = __ldg(row + t + 256);
            acc2.x += v2.x; acc2.y += v2.y;
        }
    }

    const float inv = (end > beg) ? 1.0f / (float)(end - beg) : 0.0f;
    __half* o = g_hagg + (size_t)dst * KPAD;
    float2 accs[3] = {acc0, acc1, acc2};
    #pragma unroll
    for (int j = 0; j < 3; ++j) {
        int p = t + j * 128;
        if (p >= P2) break;
        float vx = (p < F2) ? accs[j].x * inv : 0.f;
        float vy = (p < F2) ? accs[j].y * inv : 0.f;
        *reinterpret_cast<half2*>(o + hperm(2 * p)) = __floats2half2_rn(vx, vy);
    }
}

__global__ __launch_bounds__(128)
void k_agg0_prep(const float* __restrict__ x,
                 const float* __restrict__ Ws, const float* __restrict__ Wn) {
    const int bx = blockIdx.x;
    if (bx < N_DST0) {
        agg0_body(bx, x);
    } else if (bx < N_DST0 + PX2_BLKS) {
        // prepx: x[:11000] -> fp16 k-permuted g_xt
        int base = (bx - N_DST0) * 256;
        #pragma unroll
        for (int u = 0; u < 2; ++u) {
            int idx = base + threadIdx.x + u * 128;
            if (idx >= N_DST0 * P2) break;
            int row = idx / P2;
            int p   = idx % P2;
            float2 v = make_float2(0.f, 0.f);
            if (p < F2) v = reinterpret_cast<const float2*>(x)[(size_t)row * F2 + p];
            __half* dst = g_xt + (size_t)row * KPAD;
            *reinterpret_cast<half2*>(dst + hperm(2 * p)) = __floats2half2_rn(v.x, v.y);
        }
    } else {
        // prepw: W (k-major) -> fp16 k-permuted n-major g_wts/g_wtn
        int base = (bx - N_DST0 - PX2_BLKS) * 256;
        #pragma unroll
        for (int u = 0; u < 2; ++u) {
            int idx = base + threadIdx.x + u * 128;
            if (idx >= 2 * 256 * KPAD) break;
            int m = idx / (256 * KPAD);
            int r = idx % (256 * KPAD);
            int n = r / KPAD;
            int k = r % KPAD;
            const float* W = m ? Wn : Ws;
            float v = (k < F_IN) ? W[(size_t)k * HID + n] : 0.0f;
            __half h = __float2half_rn(v);
            int d = n * KPAD + hperm(k);
            if (m) g_wtn[d] = h;
            else   g_wts[d] = h;
        }
    }
}

// ---------------- tensor-core GEMM via mma.sync (FP16, sm_80+ PTX) ----------
// h = relu([Xd | Hagg] @ [Ws; Wn] + b0), fp16 operands, fp32 accumulate.
// CTA tile 128x64; grid (86, 4); 8 warps; warp tile 32x32; m16n8k16; BK=64;
// 20 flattened chunks, 2-stage cp.async; k-permuted LDS.64 fragments.
#define BK        64
#define ROWPH     80                       // padded row length (halves)
#define ROWB      (ROWPH * 2)              // 160 B
#define A_T       (128 * ROWB)             // 20480 B
#define B_T       (64 * ROWB)              // 10240 B
#define BUF_SZ    (A_T + B_T)              // 30720 B
#define GEMM_SMEM (2 * BUF_SZ)             // 61440 B
#define NCH       (2 * KCH)                // 20

#define CP16(dst, src, pred) \
    asm volatile("cp.async.cg.shared.global [%0], [%1], 16, %2;" \
                 :: "r"(dst), "l"(src), "r"(pred))
#define CP_COMMIT() asm volatile("cp.async.commit_group;" ::: "memory")
#define CP_WAIT(n)  asm volatile("cp.async.wait_group %0;" :: "n"(n) : "memory")

__device__ __forceinline__ uint32_t smem_u32(const void* p) {
    uint32_t a;
    asm("{ .reg .u64 t; cvta.to.shared.u64 t, %1; cvt.u32.u64 %0, t; }" : "=r"(a) : "l"(p));
    return a;
}

__device__ __forceinline__ void mma_f16(float* d,
                                        const uint32_t* a, const uint32_t* b) {
    asm volatile(
        "mma.sync.aligned.m16n8k16.row.col.f32.f16.f16.f32 "
        "{%0,%1,%2,%3}, {%4,%5,%6,%7}, {%8,%9}, {%0,%1,%2,%3};"
        : "+f"(d[0]), "+f"(d[1]), "+f"(d[2]), "+f"(d[3])
        : "r"(a[0]), "r"(a[1]), "r"(a[2]), "r"(a[3]), "r"(b[0]), "r"(b[1]));
}

__global__ __launch_bounds__(256, 3)
void k_gemm_mma(const float* __restrict__ bias) {
    extern __shared__ char smem[];
    const uint32_t sb = smem_u32(smem);
    const int tid  = threadIdx.x;
    const int lane = tid & 31;
    const int wid  = tid >> 5;
    const int warpM = wid & 3;
    const int warpN = wid >> 2;
    const int g  = lane >> 2;
    const int tg = lane & 3;
    const int rowBase = blockIdx.x * 128;
    const int colBase = blockIdx.y * 64;

    auto issue = [&](int c) {
        const int ph = (c >= KCH);
        const int kb = (c - ph * KCH) * BK;            // half-index
        const __half* A = ph ? g_hagg : g_xt;
        const __half* B = ph ? g_wtn : g_wts;
        const uint32_t bufb = sb + (uint32_t)(c & 1) * BUF_SZ;

        #pragma unroll
        for (int u = 0; u < 4; ++u) {
            int idx = tid + u * 256;          // 0..1023
            int row = idx >> 3, v = idx & 7;
            int grow = rowBase + row;
            int pr = (grow < N_DST0) ? 16 : 0;
            size_t gb = ((size_t)grow * KPAD + kb) * 2 + v * 16;
            if (grow >= N_DST0) gb = 0;
            uint32_t so = bufb + (uint32_t)(row * ROWB + v * 16);
            CP16(so, (const char*)A + gb, pr);
        }
        #pragma unroll
        for (int u = 0; u < 2; ++u) {
            int idx = tid + u * 256;          // 0..511
            int row = idx >> 3, v = idx & 7;
            size_t gb = ((size_t)(colBase + row) * KPAD + kb) * 2 + v * 16;
            uint32_t so = bufb + (uint32_t)(A_T + row * ROWB + v * 16);
            CP16(so, (const char*)B + gb, 16);
        }
    };

    float acc[2][4][4] = {};

    issue(0);
    CP_COMMIT();

    for (int c = 0; c < NCH; ++c) {
        if (c + 1 < NCH) { issue(c + 1); CP_COMMIT(); CP_WAIT(1); }
        else             { CP_WAIT(0); }
        __syncthreads();

        const char* buf = smem + (c & 1) * BUF_SZ;
        const char* As = buf;
        const char* Bs = buf + A_T;

        #pragma unroll
        for (int ks = 0; ks < 4; ++ks) {
            const int koff = ks * 32 + tg * 8;

            uint32_t a[2][4];
            #pragma unroll
            for (int mt = 0; mt < 2; ++mt) {
                int r0 = warpM * 32 + mt * 16 + g;
                uint2 lo = *(const uint2*)(As + r0 * ROWB + koff);
                uint2 hi = *(const uint2*)(As + (r0 + 8) * ROWB + koff);
                a[mt][0] = lo.x;
                a[mt][1] = hi.x;
                a[mt][2] = lo.y;
                a[mt][3] = hi.y;
            }
            uint32_t b[4][2];
            #pragma unroll
            for (int nt = 0; nt < 4; ++nt) {
                int r = warpN * 32 + nt * 8 + g;
                uint2 bb = *(const uint2*)(Bs + r * ROWB + koff);
                b[nt][0] = bb.x;
                b[nt][1] = bb.y;
            }
            #pragma unroll
            for (int mt = 0; mt < 2; ++mt)
                #pragma unroll
                for (int nt = 0; nt < 4; ++nt)
                    mma_f16(acc[mt][nt], a[mt], b[nt]);
        }
        __syncthreads();
    }

    // ---- epilogue: bias + relu, float2 stores ----
    float2 bv[4];
    #pragma unroll
    for (int nt = 0; nt < 4; ++nt) {
        int col = colBase + warpN * 32 + nt * 8 + tg * 2;
        bv[nt].x = __ldg(bias + col);
        bv[nt].y = __ldg(bias + col + 1);
    }
    #pragma unroll
    for (int mt = 0; mt < 2; ++mt) {
        #pragma unroll
        for (int half = 0; half < 2; ++half) {
            int row = rowBase + warpM * 32 + mt * 16 + g + half * 8;
            if (row >= N_DST0) continue;
            #pragma unroll
            for (int nt = 0; nt < 4; ++nt) {
                int col = colBase + warpN * 32 + nt * 8 + tg * 2;
                float2 o;
                o.x = fmaxf(acc[mt][nt][half * 2 + 0] + bv[nt].x, 0.f);
                o.y = fmaxf(acc[mt][nt][half * 2 + 1] + bv[nt].y, 0.f);
                *(float2*)(g_h + (size_t)row * HID + col) = o;
            }
        }
    }
}

// ---------------- fused layer-1 aggregation + output layer -------------------
__global__ __launch_bounds__(256)
void k_agg1_out(const float* __restrict__ Ws1,
                const float* __restrict__ Wn1,
                const float* __restrict__ b1,
                float* __restrict__ out) {
    __shared__ float hd[HID];
    __shared__ float ha[HID];
    const int dst = blockIdx.x;
    const int t   = threadIdx.x;

    const int beg = g_off1[dst];
    const int end = g_off1[dst + 1];
    float acc = 0.f;
    for (int e = beg; e < end; ++e)
        acc += g_h[(size_t)g_src1[e] * HID + t];
    const float inv = (end > beg) ? 1.0f / (float)(end - beg) : 0.0f;
    ha[t] = acc * inv;
    hd[t] = g_h[(size_t)dst * HID + t];     // h_dst1 = h[:1000]
    __syncthreads();

    if (t < NCLS) {
        float s = b1[t];
        #pragma unroll 4
        for (int k = 0; k < HID; ++k)
            s += hd[k] * Ws1[k * NCLS + t] + ha[k] * Wn1[k * NCLS + t];
        out[dst * NCLS + t] = s;
    }
}

// ---------------- launch (single stream, graph-capture safe) -----------------
extern "C" void kernel_launch(void* const* d_in, const int* in_sizes, int n_in,
                              void* d_out, int out_size) {
    const float* x      = (const float*)d_in[0];
    const float* Wself0 = (const float*)d_in[1];
    const float* Wneigh0= (const float*)d_in[2];
    const float* b0     = (const float*)d_in[3];
    const float* Wself1 = (const float*)d_in[4];
    const float* Wneigh1= (const float*)d_in[5];
    const float* b1     = (const float*)d_in[6];
    const int*   e0_src = (const int*)d_in[7];
    const int*   e0_dst = (const int*)d_in[8];
    const int*   e1_src = (const int*)d_in[9];
    const int*   e1_dst = (const int*)d_in[10];
    float* out = (float*)d_out;

    static bool attr_set = false;
    if (!attr_set) {
        cudaFuncSetAttribute(k_gemm_mma, cudaFuncAttributeMaxDynamicSharedMemorySize, GEMM_SMEM);
        attr_set = true;
    }

    k_zero      <<<(N_DST0 + 255) / 256, 256>>>();
    k_count     <<<(N_E0 + 255) / 256, 256>>>(e0_dst, e1_dst);
    k_scan      <<<2, 1024>>>();
    k_scatter   <<<(N_E0 + 255) / 256, 256>>>(e0_src, e0_dst, e1_src, e1_dst);
    k_agg0_prep <<<MEGA_BLKS, 128>>>(x, Wself0, Wneigh0);
    k_gemm_mma  <<<dim3((N_DST0 + 127) / 128, 4), 256, GEMM_SMEM>>>(b0);
    k_agg1_out  <<<N_DST1, 256>>>(Wself1, Wneigh1, b1, out);
}

// round 15
// speedup vs baseline: 1.3372x; 1.0083x over previous
#include <cuda_runtime.h>
#include <cuda_fp16.h>
#include <cstdint>
#include <cstddef>

// Problem constants
#define N_SRC0   286000
#define N_DST0   11000
#define N_E0     275000
#define N_DST1   1000
#define N_E1     10000
#define F_IN     602
#define HID      256
#define NCLS     41
#define KPAD     640          // 10 chunks of 64 (fp16 path)
#define F2       (F_IN / 2)   // 301
#define P2       (KPAD / 2)   // 320
#define KCH      10           // K64-chunks per phase

// k-permutation within each 16-k group: [k0k1 k8k9 | k2k3 k10k11 | k4k5 k12k13 | k6k7 k14k15]
__device__ __forceinline__ int hperm(int k) {
    int kk = k & 15;
    int p = kk >> 1, b = kk & 1;
    int o = (p < 4) ? (p * 4 + b) : ((p - 4) * 4 + 2 + b);
    return (k & ~15) | o;
}

// ---------------- scratch (device globals; zero-initialized at load) --------
__device__ int g_cnt0[N_DST0];          // zeroed by k_scan after each use
__device__ int g_off0[N_DST0 + 1];
__device__ int g_src0[N_E0];
__device__ int g_rank0[N_E0];
__device__ int g_cnt1[N_DST1];
__device__ int g_off1[N_DST1 + 1];
__device__ int g_src1[N_E1];
__device__ int g_rank1[N_E1];

// fp16 operand buffers, k-permuted layout (padded to KPAD)
__device__ __align__(16) __half g_xt  [(size_t)N_DST0 * KPAD];
__device__ __align__(16) __half g_hagg[(size_t)N_DST0 * KPAD];
__device__ __align__(16) __half g_wts [256 * KPAD];              // Wself0^T  [n][k]
__device__ __align__(16) __half g_wtn [256 * KPAD];              // Wneigh0^T [n][k]

__device__ float g_h[(size_t)N_DST0 * HID];

// ---------------- CSR build --------------------------------------------------
// count: the atomic's return value IS the edge's within-dst rank; store it so
// scatter needs no second atomic. (g_cnt starts zero: zero-init at load, then
// re-zeroed by k_scan every run.)
__global__ void k_count(const int* __restrict__ e0_dst, const int* __restrict__ e1_dst) {
    int i = blockIdx.x * blockDim.x + threadIdx.x;
    if (i < N_E0) g_rank0[i] = atomicAdd(&g_cnt0[e0_dst[i]], 1);
    if (i < N_E1) g_rank1[i] = atomicAdd(&g_cnt1[e1_dst[i]], 1);
}

// scan: exclusive prefix of cnt -> off, and re-zero cnt for the next replay
__device__ void scan_excl(int* cnt, int* off, int n) {
    __shared__ int wsum[32];
    __shared__ int carry;
    const int t = threadIdx.x, lane = t & 31, w = t >> 5;
    if (t == 0) carry = 0;
    __syncthreads();
    for (int base = 0; base < n; base += 1024) {
        int i = base + t;
        int v = (i < n) ? cnt[i] : 0;
        int s = v;
        #pragma unroll
        for (int d = 1; d < 32; d <<= 1) { int u = __shfl_up_sync(~0u, s, d); if (lane >= d) s += u; }
        if (lane == 31) wsum[w] = s;
        __syncthreads();
        if (w == 0) {
            int ws = wsum[lane];
            #pragma unroll
            for (int d = 1; d < 32; d <<= 1) { int u = __shfl_up_sync(~0u, ws, d); if (lane >= d) ws += u; }
            wsum[lane] = ws;
        }
        __syncthreads();
        int woff = (w > 0) ? wsum[w - 1] : 0;
        if (i < n) { off[i] = carry + woff + s - v; cnt[i] = 0; }
        __syncthreads();
        if (t == 0) carry += wsum[31];
        __syncthreads();
    }
    if (threadIdx.x == 0) off[n] = carry;
}

__global__ void k_scan() {
    if (blockIdx.x == 0) scan_excl(g_cnt0, g_off0, N_DST0);
    else                 scan_excl(g_cnt1, g_off1, N_DST1);
}

// scatter: atomic-free (rank precomputed in k_count)
__global__ void k_scatter(const int* __restrict__ e0_src, const int* __restrict__ e0_dst,
                          const int* __restrict__ e1_src, const int* __restrict__ e1_dst) {
    int i = blockIdx.x * blockDim.x + threadIdx.x;
    if (i < N_E0)
        g_src0[g_off0[e0_dst[i]] + g_rank0[i]] = e0_src[i];
    if (i < N_E1)
        g_src1[g_off1[e1_dst[i]] + g_rank1[i]] = e1_src[i];
}

// ---------------- mega kernel: agg0 (first) + prepx + prepw filler ----------
#define PX2_BLKS ((N_DST0 * P2 + 255) / 256)     // 13750
#define PW2_BLKS ((2 * 256 * KPAD + 255) / 256)  // 1280
#define MEGA_BLKS (N_DST0 + PX2_BLKS + PW2_BLKS)

__device__ __forceinline__ void agg0_body(int dst, const float* __restrict__ x) {
    const int beg = g_off0[dst];
    const int end = g_off0[dst + 1];
    const int t   = threadIdx.x;

    float2 acc0 = make_float2(0.f, 0.f);
    float2 acc1 = make_float2(0.f, 0.f);
    float2 acc2 = make_float2(0.f, 0.f);
    const bool has3 = (t + 256) < F2;

    int e = beg;
    for (; e + 4 <= end; e += 4) {
        const float2* r0 = reinterpret_cast<const float2*>(x + (size_t)g_src0[e + 0] * F_IN);
        const float2* r1 = reinterpret_cast<const float2*>(x + (size_t)g_src0[e + 1] * F_IN);
        const float2* r2 = reinterpret_cast<const float2*>(x + (size_t)g_src0[e + 2] * F_IN);
        const float2* r3 = reinterpret_cast<const float2*>(x + (size_t)g_src0[e + 3] * F_IN);
        float2 a0 = __ldg(r0 + t),       b0 = __ldg(r1 + t),       c0 = __ldg(r2 + t),       d0 = __ldg(r3 + t);
        float2 a1 = __ldg(r0 + t + 128), b1 = __ldg(r1 + t + 128), c1 = __ldg(r2 + t + 128), d1 = __ldg(r3 + t + 128);
        acc0.x += a0.x + b0.x + c0.x + d0.x;
        acc0.y += a0.y + b0.y + c0.y + d0.y;
        acc1.x += a1.x + b1.x + c1.x + d1.x;
        acc1.y += a1.y + b1.y + c1.y + d1.y;
        if (has3) {
            float2 a2 = __ldg(r0 + t + 256), b2 = __ldg(r1 + t + 256);
            float2 c2 = __ldg(r2 + t + 256), d2 = __ldg(r3 + t + 256);
            acc2.x += a2.x + b2.x + c2.x + d2.x;
            acc2.y += a2.y + b2.y + c2.y + d2.y;
        }
    }
    for (; e < end; ++e) {
        const float2* row = reinterpret_cast<const float2*>(x + (size_t)g_src0[e] * F_IN);
        float2 v0 = __ldg(row + t);
        float2 v1 = __ldg(row + t + 128);
        acc0.x += v0.x; acc0.y += v0.y;
        acc1.x += v1.x; acc1.y += v1.y;
        if (has3) {
            float2 v2 = __ldg(row + t + 256);
            acc2.x += v2.x; acc2.y += v2.y;
        }
    }

    const float inv = (end > beg) ? 1.0f / (float)(end - beg) : 0.0f;
    __half* o = g_hagg + (size_t)dst * KPAD;
    float2 accs[3] = {acc0, acc1, acc2};
    #pragma unroll
    for (int j = 0; j < 3; ++j) {
        int p = t + j * 128;
        if (p >= P2) break;
        float vx = (p < F2) ? accs[j].x * inv : 0.f;
        float vy = (p < F2) ? accs[j].y * inv : 0.f;
        *reinterpret_cast<half2*>(o + hperm(2 * p)) = __floats2half2_rn(vx, vy);
    }
}

__global__ __launch_bounds__(128)
void k_agg0_prep(const float* __restrict__ x,
                 const float* __restrict__ Ws, const float* __restrict__ Wn) {
    const int bx = blockIdx.x;
    if (bx < N_DST0) {
        agg0_body(bx, x);
    } else if (bx < N_DST0 + PX2_BLKS) {
        int base = (bx - N_DST0) * 256;
        #pragma unroll
        for (int u = 0; u < 2; ++u) {
            int idx = base + threadIdx.x + u * 128;
            if (idx >= N_DST0 * P2) break;
            int row = idx / P2;
            int p   = idx % P2;
            float2 v = make_float2(0.f, 0.f);
            if (p < F2) v = reinterpret_cast<const float2*>(x)[(size_t)row * F2 + p];
            __half* dst = g_xt + (size_t)row * KPAD;
            *reinterpret_cast<half2*>(dst + hperm(2 * p)) = __floats2half2_rn(v.x, v.y);
        }
    } else {
        int base = (bx - N_DST0 - PX2_BLKS) * 256;
        #pragma unroll
        for (int u = 0; u < 2; ++u) {
            int idx = base + threadIdx.x + u * 128;
            if (idx >= 2 * 256 * KPAD) break;
            int m = idx / (256 * KPAD);
            int r = idx % (256 * KPAD);
            int n = r / KPAD;
            int k = r % KPAD;
            const float* W = m ? Wn : Ws;
            float v = (k < F_IN) ? W[(size_t)k * HID + n] : 0.0f;
            __half h = __float2half_rn(v);
            int d = n * KPAD + hperm(k);
            if (m) g_wtn[d] = h;
            else   g_wts[d] = h;
        }
    }
}

// ---------------- tensor-core GEMM via mma.sync (FP16, sm_80+ PTX) ----------
#define BK        64
#define ROWPH     80                       // padded row length (halves)
#define ROWB      (ROWPH * 2)              // 160 B
#define A_T       (128 * ROWB)             // 20480 B
#define B_T       (64 * ROWB)              // 10240 B
#define BUF_SZ    (A_T + B_T)              // 30720 B
#define GEMM_SMEM (2 * BUF_SZ)             // 61440 B
#define NCH       (2 * KCH)                // 20

#define CP16(dst, src, pred) \
    asm volatile("cp.async.cg.shared.global [%0], [%1], 16, %2;" \
                 :: "r"(dst), "l"(src), "r"(pred))
#define CP_COMMIT() asm volatile("cp.async.commit_group;" ::: "memory")
#define CP_WAIT(n)  asm volatile("cp.async.wait_group %0;" :: "n"(n) : "memory")

__device__ __forceinline__ uint32_t smem_u32(const void* p) {
    uint32_t a;
    asm("{ .reg .u64 t; cvta.to.shared.u64 t, %1; cvt.u32.u64 %0, t; }" : "=r"(a) : "l"(p));
    return a;
}

__device__ __forceinline__ void mma_f16(float* d,
                                        const uint32_t* a, const uint32_t* b) {
    asm volatile(
        "mma.sync.aligned.m16n8k16.row.col.f32.f16.f16.f32 "
        "{%0,%1,%2,%3}, {%4,%5,%6,%7}, {%8,%9}, {%0,%1,%2,%3};"
        : "+f"(d[0]), "+f"(d[1]), "+f"(d[2]), "+f"(d[3])
        : "r"(a[0]), "r"(a[1]), "r"(a[2]), "r"(a[3]), "r"(b[0]), "r"(b[1]));
}

__global__ __launch_bounds__(256, 3)
void k_gemm_mma(const float* __restrict__ bias) {
    extern __shared__ char smem[];
    const uint32_t sb = smem_u32(smem);
    const int tid  = threadIdx.x;
    const int lane = tid & 31;
    const int wid  = tid >> 5;
    const int warpM = wid & 3;
    const int warpN = wid >> 2;
    const int g  = lane >> 2;
    const int tg = lane & 3;
    const int rowBase = blockIdx.x * 128;
    const int colBase = blockIdx.y * 64;

    auto issue = [&](int c) {
        const int ph = (c >= KCH);
        const int kb = (c - ph * KCH) * BK;            // half-index
        const __half* A = ph ? g_hagg : g_xt;
        const __half* B = ph ? g_wtn : g_wts;
        const uint32_t bufb = sb + (uint32_t)(c & 1) * BUF_SZ;

        #pragma unroll
        for (int u = 0; u < 4; ++u) {
            int idx = tid + u * 256;          // 0..1023
            int row = idx >> 3, v = idx & 7;
            int grow = rowBase + row;
            int pr = (grow < N_DST0) ? 16 : 0;
            size_t gb = ((size_t)grow * KPAD + kb) * 2 + v * 16;
            if (grow >= N_DST0) gb = 0;
            uint32_t so = bufb + (uint32_t)(row * ROWB + v * 16);
            CP16(so, (const char*)A + gb, pr);
        }
        #pragma unroll
        for (int u = 0; u < 2; ++u) {
            int idx = tid + u * 256;          // 0..511
            int row = idx >> 3, v = idx & 7;
            size_t gb = ((size_t)(colBase + row) * KPAD + kb) * 2 + v * 16;
            uint32_t so = bufb + (uint32_t)(A_T + row * ROWB + v * 16);
            CP16(so, (const char*)B + gb, 16);
        }
    };

    float acc[2][4][4] = {};

    issue(0);
    CP_COMMIT();

    for (int c = 0; c < NCH; ++c) {
        if (c + 1 < NCH) { issue(c + 1); CP_COMMIT(); CP_WAIT(1); }
        else             { CP_WAIT(0); }
        __syncthreads();

        const char* buf = smem + (c & 1) * BUF_SZ;
        const char* As = buf;
        const char* Bs = buf + A_T;

        #pragma unroll
        for (int ks = 0; ks < 4; ++ks) {
            const int koff = ks * 32 + tg * 8;

            uint32_t a[2][4];
            #pragma unroll
            for (int mt = 0; mt < 2; ++mt) {
                int r0 = warpM * 32 + mt * 16 + g;
                uint2 lo = *(const uint2*)(As + r0 * ROWB + koff);
                uint2 hi = *(const uint2*)(As + (r0 + 8) * ROWB + koff);
                a[mt][0] = lo.x;
                a[mt][1] = hi.x;
                a[mt][2] = lo.y;
                a[mt][3] = hi.y;
            }
            uint32_t b[4][2];
            #pragma unroll
            for (int nt = 0; nt < 4; ++nt) {
                int r = warpN * 32 + nt * 8 + g;
                uint2 bb = *(const uint2*)(Bs + r * ROWB + koff);
                b[nt][0] = bb.x;
                b[nt][1] = bb.y;
            }
            #pragma unroll
            for (int mt = 0; mt < 2; ++mt)
                #pragma unroll
                for (int nt = 0; nt < 4; ++nt)
                    mma_f16(acc[mt][nt], a[mt], b[nt]);
        }
        __syncthreads();
    }

    // ---- epilogue: bias + relu, float2 stores ----
    float2 bv[4];
    #pragma unroll
    for (int nt = 0; nt < 4; ++nt) {
        int col = colBase + warpN * 32 + nt * 8 + tg * 2;
        bv[nt].x = __ldg(bias + col);
        bv[nt].y = __ldg(bias + col + 1);
    }
    #pragma unroll
    for (int mt = 0; mt < 2; ++mt) {
        #pragma unroll
        for (int half = 0; half < 2; ++half) {
            int row = rowBase + warpM * 32 + mt * 16 + g + half * 8;
            if (row >= N_DST0) continue;
            #pragma unroll
            for (int nt = 0; nt < 4; ++nt) {
                int col = colBase + warpN * 32 + nt * 8 + tg * 2;
                float2 o;
                o.x = fmaxf(acc[mt][nt][half * 2 + 0] + bv[nt].x, 0.f);
                o.y = fmaxf(acc[mt][nt][half * 2 + 1] + bv[nt].y, 0.f);
                *(float2*)(g_h + (size_t)row * HID + col) = o;
            }
        }
    }
}

// ---------------- fused layer-1 aggregation + output layer -------------------
__global__ __launch_bounds__(256)
void k_agg1_out(const float* __restrict__ Ws1,
                const float* __restrict__ Wn1,
                const float* __restrict__ b1,
                float* __restrict__ out) {
    __shared__ float hd[HID];
    __shared__ float ha[HID];
    const int dst = blockIdx.x;
    const int t   = threadIdx.x;

    const int beg = g_off1[dst];
    const int end = g_off1[dst + 1];
    float acc = 0.f;
    for (int e = beg; e < end; ++e)
        acc += g_h[(size_t)g_src1[e] * HID + t];
    const float inv = (end > beg) ? 1.0f / (float)(end - beg) : 0.0f;
    ha[t] = acc * inv;
    hd[t] = g_h[(size_t)dst * HID + t];     // h_dst1 = h[:1000]
    __syncthreads();

    if (t < NCLS) {
        float s = b1[t];
        #pragma unroll 4
        for (int k = 0; k < HID; ++k)
            s += hd[k] * Ws1[k * NCLS + t] + ha[k] * Wn1[k * NCLS + t];
        out[dst * NCLS + t] = s;
    }
}

// ---------------- launch (single stream, graph-capture safe) -----------------
extern "C" void kernel_launch(void* const* d_in, const int* in_sizes, int n_in,
                              void* d_out, int out_size) {
    const float* x      = (const float*)d_in[0];
    const float* Wself0 = (const float*)d_in[1];
    const float* Wneigh0= (const float*)d_in[2];
    const float* b0     = (const float*)d_in[3];
    const float* Wself1 = (const float*)d_in[4];
    const float* Wneigh1= (const float*)d_in[5];
    const float* b1     = (const float*)d_in[6];
    const int*   e0_src = (const int*)d_in[7];
    const int*   e0_dst = (const int*)d_in[8];
    const int*   e1_src = (const int*)d_in[9];
    const int*   e1_dst = (const int*)d_in[10];
    float* out = (float*)d_out;

    static bool attr_set = false;
    if (!attr_set) {
        cudaFuncSetAttribute(k_gemm_mma, cudaFuncAttributeMaxDynamicSharedMemorySize, GEMM_SMEM);
        attr_set = true;
    }

    k_count     <<<(N_E0 + 255) / 256, 256>>>(e0_dst, e1_dst);
    k_scan      <<<2, 1024>>>();
    k_scatter   <<<(N_E0 + 255) / 256, 256>>>(e0_src, e0_dst, e1_src, e1_dst);
    k_agg0_prep <<<MEGA_BLKS, 128>>>(x, Wself0, Wneigh0);
    k_gemm_mma  <<<dim3((N_DST0 + 127) / 128, 4), 256, GEMM_SMEM>>>(b0);
    k_agg1_out  <<<N_DST1, 256>>>(Wself1, Wneigh1, b1, out);
}

// round 16
// speedup vs baseline: 1.3561x; 1.0142x over previous
#include <cuda_runtime.h>
#include <cuda_fp16.h>
#include <cstdint>
#include <cstddef>

// Problem constants
#define N_SRC0   286000
#define N_DST0   11000
#define N_E0     275000
#define N_DST1   1000
#define N_E1     10000
#define F_IN     602
#define HID      256
#define NCLS     41
#define KPAD     640          // 10 chunks of 64 (fp16 path)
#define F2       (F_IN / 2)   // 301
#define P2       (KPAD / 2)   // 320
#define KCH      10           // K64-chunks per phase

// k-permutation within each 16-k group: [k0k1 k8k9 | k2k3 k10k11 | k4k5 k12k13 | k6k7 k14k15]
__device__ __forceinline__ int hperm(int k) {
    int kk = k & 15;
    int p = kk >> 1, b = kk & 1;
    int o = (p < 4) ? (p * 4 + b) : ((p - 4) * 4 + 2 + b);
    return (k & ~15) | o;
}

// ---------------- scratch (device globals; zero-initialized at load) --------
__device__ int g_cnt0[N_DST0];          // zeroed by k_scan after each use
__device__ int g_off0[N_DST0 + 1];
__device__ int g_src0[N_E0];
__device__ int g_rank0[N_E0];
__device__ int g_cnt1[N_DST1];
__device__ int g_off1[N_DST1 + 1];
__device__ int g_src1[N_E1];
__device__ int g_rank1[N_E1];

// fp16 operand buffers, k-permuted layout (padded to KPAD)
__device__ __align__(16) __half g_xt  [(size_t)N_DST0 * KPAD];
__device__ __align__(16) __half g_hagg[(size_t)N_DST0 * KPAD];
__device__ __align__(16) __half g_wts [256 * KPAD];              // Wself0^T  [n][k]
__device__ __align__(16) __half g_wtn [256 * KPAD];              // Wneigh0^T [n][k]

__device__ float g_h[(size_t)N_DST0 * HID];

// ---------------- CSR build --------------------------------------------------
__global__ void k_count(const int* __restrict__ e0_dst, const int* __restrict__ e1_dst) {
    int i = blockIdx.x * blockDim.x + threadIdx.x;
    if (i < N_E0) g_rank0[i] = atomicAdd(&g_cnt0[e0_dst[i]], 1);
    if (i < N_E1) g_rank1[i] = atomicAdd(&g_cnt1[e1_dst[i]], 1);
}

// scan: exclusive prefix of cnt -> off, re-zeroing cnt for the next replay
__device__ void scan_excl(int* cnt, int* off, int n) {
    __shared__ int wsum[32];
    __shared__ int carry;
    const int t = threadIdx.x, lane = t & 31, w = t >> 5;
    if (t == 0) carry = 0;
    __syncthreads();
    for (int base = 0; base < n; base += 1024) {
        int i = base + t;
        int v = (i < n) ? cnt[i] : 0;
        int s = v;
        #pragma unroll
        for (int d = 1; d < 32; d <<= 1) { int u = __shfl_up_sync(~0u, s, d); if (lane >= d) s += u; }
        if (lane == 31) wsum[w] = s;
        __syncthreads();
        if (w == 0) {
            int ws = wsum[lane];
            #pragma unroll
            for (int d = 1; d < 32; d <<= 1) { int u = __shfl_up_sync(~0u, ws, d); if (lane >= d) ws += u; }
            wsum[lane] = ws;
        }
        __syncthreads();
        int woff = (w > 0) ? wsum[w - 1] : 0;
        if (i < n) { off[i] = carry + woff + s - v; cnt[i] = 0; }
        __syncthreads();
        if (t == 0) carry += wsum[31];
        __syncthreads();
    }
    if (threadIdx.x == 0) off[n] = carry;
}

__global__ void k_scan() {
    if (blockIdx.x == 0) scan_excl(g_cnt0, g_off0, N_DST0);
    else                 scan_excl(g_cnt1, g_off1, N_DST1);
}

// scatter: atomic-free (rank precomputed in k_count)
__global__ void k_scatter(const int* __restrict__ e0_src, const int* __restrict__ e0_dst,
                          const int* __restrict__ e1_src, const int* __restrict__ e1_dst) {
    int i = blockIdx.x * blockDim.x + threadIdx.x;
    if (i < N_E0)
        g_src0[g_off0[e0_dst[i]] + g_rank0[i]] = e0_src[i];
    if (i < N_E1)
        g_src1[g_off1[e1_dst[i]] + g_rank1[i]] = e1_src[i];
}

// ---------------- mega kernel: agg0 (first) + prepx + prepw filler ----------
#define PX2_BLKS ((N_DST0 * P2 + 255) / 256)     // 13750
#define PW2_BLKS ((2 * 256 * KPAD + 255) / 256)  // 1280
#define MEGA_BLKS (N_DST0 + PX2_BLKS + PW2_BLKS)

__device__ __forceinline__ void agg0_body(int dst, const float* __restrict__ x) {
    const int beg = g_off0[dst];
    const int end = g_off0[dst + 1];
    const int t   = threadIdx.x;

    float2 acc0 = make_float2(0.f, 0.f);
    float2 acc1 = make_float2(0.f, 0.f);
    float2 acc2 = make_float2(0.f, 0.f);
    const bool has3 = (t + 256) < F2;

    int e = beg;
    if (e + 4 <= end) {
        // software-pipelined 4-edge unroll: next iteration's src indices are
        // hoisted ahead of the accumulate so all 12 LDG.64 stay in flight.
        int s0 = g_src0[e + 0], s1 = g_src0[e + 1], s2 = g_src0[e + 2], s3 = g_src0[e + 3];
        for (; e + 4 <= end; ) {
            const float2* r0 = reinterpret_cast<const float2*>(x + (size_t)s0 * F_IN);
            const float2* r1 = reinterpret_cast<const float2*>(x + (size_t)s1 * F_IN);
            const float2* r2 = reinterpret_cast<const float2*>(x + (size_t)s2 * F_IN);
            const float2* r3 = reinterpret_cast<const float2*>(x + (size_t)s3 * F_IN);
            float2 a0 = __ldg(r0 + t),       b0 = __ldg(r1 + t),       c0 = __ldg(r2 + t),       d0 = __ldg(r3 + t);
            float2 a1 = __ldg(r0 + t + 128), b1 = __ldg(r1 + t + 128), c1 = __ldg(r2 + t + 128), d1 = __ldg(r3 + t + 128);
            float2 a2, b2, c2, d2;
            if (has3) {
                a2 = __ldg(r0 + t + 256); b2 = __ldg(r1 + t + 256);
                c2 = __ldg(r2 + t + 256); d2 = __ldg(r3 + t + 256);
            }
            e += 4;
            if (e + 4 <= end) {   // prefetch next indices before consuming loads
                s0 = g_src0[e + 0]; s1 = g_src0[e + 1];
                s2 = g_src0[e + 2]; s3 = g_src0[e + 3];
            }
            acc0.x += a0.x + b0.x + c0.x + d0.x;
            acc0.y += a0.y + b0.y + c0.y + d0.y;
            acc1.x += a1.x + b1.x + c1.x + d1.x;
            acc1.y += a1.y + b1.y + c1.y + d1.y;
            if (has3) {
                acc2.x += a2.x + b2.x + c2.x + d2.x;
                acc2.y += a2.y + b2.y + c2.y + d2.y;
            }
        }
    }
    for (; e < end; ++e) {
        const float2* row = reinterpret_cast<const float2*>(x + (size_t)g_src0[e] * F_IN);
        float2 v0 = __ldg(row + t);
        float2 v1 = __ldg(row + t + 128);
        acc0.x += v0.x; acc0.y += v0.y;
        acc1.x += v1.x; acc1.y += v1.y;
        if (has3) {
            float2 v2 = __ldg(row + t + 256);
            acc2.x += v2.x; acc2.y += v2.y;
        }
    }

    const float inv = (end > beg) ? 1.0f / (float)(end - beg) : 0.0f;
    __half* o = g_hagg + (size_t)dst * KPAD;
    float2 accs[3] = {acc0, acc1, acc2};
    #pragma unroll
    for (int j = 0; j < 3; ++j) {
        int p = t + j * 128;
        if (p >= P2) break;
        float vx = (p < F2) ? accs[j].x * inv : 0.f;
        float vy = (p < F2) ? accs[j].y * inv : 0.f;
        *reinterpret_cast<half2*>(o + hperm(2 * p)) = __floats2half2_rn(vx, vy);
    }
}

// launch_bounds(128, 8): 64-reg budget so the 12-load flight group is not
// serialized by a 32-reg occupancy cap (ncu R14: regs=32, DRAM 72.5%).
__global__ __launch_bounds__(128, 8)
void k_agg0_prep(const float* __restrict__ x,
                 const float* __restrict__ Ws, const float* __restrict__ Wn) {
    const int bx = blockIdx.x;
    if (bx < N_DST0) {
        agg0_body(bx, x);
    } else if (bx < N_DST0 + PX2_BLKS) {
        int base = (bx - N_DST0) * 256;
        #pragma unroll
        for (int u = 0; u < 2; ++u) {
            int idx = base + threadIdx.x + u * 128;
            if (idx >= N_DST0 * P2) break;
            int row = idx / P2;
            int p   = idx % P2;
            float2 v = make_float2(0.f, 0.f);
            if (p < F2) v = reinterpret_cast<const float2*>(x)[(size_t)row * F2 + p];
            __half* dst = g_xt + (size_t)row * KPAD;
            *reinterpret_cast<half2*>(dst + hperm(2 * p)) = __floats2half2_rn(v.x, v.y);
        }
    } else {
        int base = (bx - N_DST0 - PX2_BLKS) * 256;
        #pragma unroll
        for (int u = 0; u < 2; ++u) {
            int idx = base + threadIdx.x + u * 128;
            if (idx >= 2 * 256 * KPAD) break;
            int m = idx / (256 * KPAD);
            int r = idx % (256 * KPAD);
            int n = r / KPAD;
            int k = r % KPAD;
            const float* W = m ? Wn : Ws;
            float v = (k < F_IN) ? W[(size_t)k * HID + n] : 0.0f;
            __half h = __float2half_rn(v);
            int d = n * KPAD + hperm(k);
            if (m) g_wtn[d] = h;
            else   g_wts[d] = h;
        }
    }
}

// ---------------- tensor-core GEMM via mma.sync (FP16, sm_80+ PTX) ----------
#define BK        64
#define ROWPH     80                       // padded row length (halves)
#define ROWB      (ROWPH * 2)              // 160 B
#define A_T       (128 * ROWB)             // 20480 B
#define B_T       (64 * ROWB)              // 10240 B
#define BUF_SZ    (A_T + B_T)              // 30720 B
#define GEMM_SMEM (2 * BUF_SZ)             // 61440 B
#define NCH       (2 * KCH)                // 20

#define CP16(dst, src, pred) \
    asm volatile("cp.async.cg.shared.global [%0], [%1], 16, %2;" \
                 :: "r"(dst), "l"(src), "r"(pred))
#define CP_COMMIT() asm volatile("cp.async.commit_group;" ::: "memory")
#define CP_WAIT(n)  asm volatile("cp.async.wait_group %0;" :: "n"(n) : "memory")

__device__ __forceinline__ uint32_t smem_u32(const void* p) {
    uint32_t a;
    asm("{ .reg .u64 t; cvta.to.shared.u64 t, %1; cvt.u32.u64 %0, t; }" : "=r"(a) : "l"(p));
    return a;
}

__device__ __forceinline__ void mma_f16(float* d,
                                        const uint32_t* a, const uint32_t* b) {
    asm volatile(
        "mma.sync.aligned.m16n8k16.row.col.f32.f16.f16.f32 "
        "{%0,%1,%2,%3}, {%4,%5,%6,%7}, {%8,%9}, {%0,%1,%2,%3};"
        : "+f"(d[0]), "+f"(d[1]), "+f"(d[2]), "+f"(d[3])
        : "r"(a[0]), "r"(a[1]), "r"(a[2]), "r"(a[3]), "r"(b[0]), "r"(b[1]));
}

__global__ __launch_bounds__(256, 3)
void k_gemm_mma(const float* __restrict__ bias) {
    extern __shared__ char smem[];
    const uint32_t sb = smem_u32(smem);
    const int tid  = threadIdx.x;
    const int lane = tid & 31;
    const int wid  = tid >> 5;
    const int warpM = wid & 3;
    const int warpN = wid >> 2;
    const int g  = lane >> 2;
    const int tg = lane & 3;
    const int rowBase = blockIdx.x * 128;
    const int colBase = blockIdx.y * 64;

    auto issue = [&](int c) {
        const int ph = (c >= KCH);
        const int kb = (c - ph * KCH) * BK;            // half-index
        const __half* A = ph ? g_hagg : g_xt;
        const __half* B = ph ? g_wtn : g_wts;
        const uint32_t bufb = sb + (uint32_t)(c & 1) * BUF_SZ;

        #pragma unroll
        for (int u = 0; u < 4; ++u) {
            int idx = tid + u * 256;          // 0..1023
            int row = idx >> 3, v = idx & 7;
            int grow = rowBase + row;
            int pr = (grow < N_DST0) ? 16 : 0;
            size_t gb = ((size_t)grow * KPAD + kb) * 2 + v * 16;
            if (grow >= N_DST0) gb = 0;
            uint32_t so = bufb + (uint32_t)(row * ROWB + v * 16);
            CP16(so, (const char*)A + gb, pr);
        }
        #pragma unroll
        for (int u = 0; u < 2; ++u) {
            int idx = tid + u * 256;          // 0..511
            int row = idx >> 3, v = idx & 7;
            size_t gb = ((size_t)(colBase + row) * KPAD + kb) * 2 + v * 16;
            uint32_t so = bufb + (uint32_t)(A_T + row * ROWB + v * 16);
            CP16(so, (const char*)B + gb, 16);
        }
    };

    float acc[2][4][4] = {};

    issue(0);
    CP_COMMIT();

    for (int c = 0; c < NCH; ++c) {
        if (c + 1 < NCH) { issue(c + 1); CP_COMMIT(); CP_WAIT(1); }
        else             { CP_WAIT(0); }
        __syncthreads();

        const char* buf = smem + (c & 1) * BUF_SZ;
        const char* As = buf;
        const char* Bs = buf + A_T;

        #pragma unroll
        for (int ks = 0; ks < 4; ++ks) {
            const int koff = ks * 32 + tg * 8;

            uint32_t a[2][4];
            #pragma unroll
            for (int mt = 0; mt < 2; ++mt) {
                int r0 = warpM * 32 + mt * 16 + g;
                uint2 lo = *(const uint2*)(As + r0 * ROWB + koff);
                uint2 hi = *(const uint2*)(As + (r0 + 8) * ROWB + koff);
                a[mt][0] = lo.x;
                a[mt][1] = hi.x;
                a[mt][2] = lo.y;
                a[mt][3] = hi.y;
            }
            uint32_t b[4][2];
            #pragma unroll
            for (int nt = 0; nt < 4; ++nt) {
                int r = warpN * 32 + nt * 8 + g;
                uint2 bb = *(const uint2*)(Bs + r * ROWB + koff);
                b[nt][0] = bb.x;
                b[nt][1] = bb.y;
            }
            #pragma unroll
            for (int mt = 0; mt < 2; ++mt)
                #pragma unroll
                for (int nt = 0; nt < 4; ++nt)
                    mma_f16(acc[mt][nt], a[mt], b[nt]);
        }
        __syncthreads();
    }

    // ---- epilogue: bias + relu, float2 stores ----
    float2 bv[4];
    #pragma unroll
    for (int nt = 0; nt < 4; ++nt) {
        int col = colBase + warpN * 32 + nt * 8 + tg * 2;
        bv[nt].x = __ldg(bias + col);
        bv[nt].y = __ldg(bias + col + 1);
    }
    #pragma unroll
    for (int mt = 0; mt < 2; ++mt) {
        #pragma unroll
        for (int half = 0; half < 2; ++half) {
            int row = rowBase + warpM * 32 + mt * 16 + g + half * 8;
            if (row >= N_DST0) continue;
            #pragma unroll
            for (int nt = 0; nt < 4; ++nt) {
                int col = colBase + warpN * 32 + nt * 8 + tg * 2;
                float2 o;
                o.x = fmaxf(acc[mt][nt][half * 2 + 0] + bv[nt].x, 0.f);
                o.y = fmaxf(acc[mt][nt][half * 2 + 1] + bv[nt].y, 0.f);
                *(float2*)(g_h + (size_t)row * HID + col) = o;
            }
        }
    }
}

// ---------------- fused layer-1 aggregation + output layer -------------------
__global__ __launch_bounds__(256)
void k_agg1_out(const float* __restrict__ Ws1,
                const float* __restrict__ Wn1,
                const float* __restrict__ b1,
                float* __restrict__ out) {
    __shared__ float hd[HID];
    __shared__ float ha[HID];
    const int dst = blockIdx.x;
    const int t   = threadIdx.x;

    const int beg = g_off1[dst];
    const int end = g_off1[dst + 1];
    float acc = 0.f;
    for (int e = beg; e < end; ++e)
        acc += g_h[(size_t)g_src1[e] * HID + t];
    const float inv = (end > beg) ? 1.0f / (float)(end - beg) : 0.0f;
    ha[t] = acc * inv;
    hd[t] = g_h[(size_t)dst * HID + t];     // h_dst1 = h[:1000]
    __syncthreads();

    if (t < NCLS) {
        float s = b1[t];
        #pragma unroll 4
        for (int k = 0; k < HID; ++k)
            s += hd[k] * Ws1[k * NCLS + t] + ha[k] * Wn1[k * NCLS + t];
        out[dst * NCLS + t] = s;
    }
}

// ---------------- launch (single stream, graph-capture safe) -----------------
extern "C" void kernel_launch(void* const* d_in, const int* in_sizes, int n_in,
                              void* d_out, int out_size) {
    const float* x      = (const float*)d_in[0];
    const float* Wself0 = (const float*)d_in[1];
    const float* Wneigh0= (const float*)d_in[2];
    const float* b0     = (const float*)d_in[3];
    const float* Wself1 = (const float*)d_in[4];
    const float* Wneigh1= (const float*)d_in[5];
    const float* b1     = (const float*)d_in[6];
    const int*   e0_src = (const int*)d_in[7];
    const int*   e0_dst = (const int*)d_in[8];
    const int*   e1_src = (const int*)d_in[9];
    const int*   e1_dst = (const int*)d_in[10];
    float* out = (float*)d_out;

    static bool attr_set = false;
    if (!attr_set) {
        cudaFuncSetAttribute(k_gemm_mma, cudaFuncAttributeMaxDynamicSharedMemorySize, GEMM_SMEM);
        attr_set = true;
    }

    k_count     <<<(N_E0 + 255) / 256, 256>>>(e0_dst, e1_dst);
    k_scan      <<<2, 1024>>>();
    k_scatter   <<<(N_E0 + 255) / 256, 256>>>(e0_src, e0_dst, e1_src, e1_dst);
    k_agg0_prep <<<MEGA_BLKS, 128>>>(x, Wself0, Wneigh0);
    k_gemm_mma  <<<dim3((N_DST0 + 127) / 128, 4), 256, GEMM_SMEM>>>(b0);
    k_agg1_out  <<<N_DST1, 256>>>(Wself1, Wneigh1, b1, out);
}